// round 1
// baseline (speedup 1.0000x reference)
#include <cuda_runtime.h>
#include <math.h>
#include <stdint.h>

#define HIDDEN 1024
#define NHEADS 16
#define NKV 4
#define HD 64
#define BATCH 2
#define SEQ 2048
#define MROWS (BATCH*SEQ)     // 4096
#define KVW (NKV*HD)          // 256

// ---------------- scratch (no allocations allowed) ----------------
__device__ float g_Q[(size_t)MROWS*HIDDEN];
__device__ float g_K[(size_t)MROWS*KVW];
__device__ float g_V[(size_t)MROWS*KVW];
__device__ float g_attn[(size_t)MROWS*HIDDEN];
__device__ float g_cos[SEQ*HD];
__device__ float g_sin[SEQ*HD];

// ---------------- generic SGEMM: C = A[MxK] @ B[KxN] + bias ----------------
#define BM 128
#define BN 128
#define BKD 16

__global__ __launch_bounds__(256)
void sgemm_bias(const float* __restrict__ A, const float* __restrict__ B,
                const float* __restrict__ bias, float* __restrict__ C,
                int M, int N, int K)
{
    __shared__ float As[BKD][BM];   // transposed A tile
    __shared__ float Bs[BKD][BN];

    int tid = threadIdx.x;
    int bm = blockIdx.y * BM;
    int bn = blockIdx.x * BN;

    int arow = tid >> 2;            // 0..63 (handles arow, arow+64)
    int acol = (tid & 3) * 4;       // 0,4,8,12
    int brow = tid >> 5;            // 0..7 (handles brow, brow+8)
    int bcol = (tid & 31) * 4;

    int tr = (tid >> 4) * 8;
    int tc = (tid & 15) * 8;

    float acc[8][8];
    #pragma unroll
    for (int i = 0; i < 8; i++)
        #pragma unroll
        for (int j = 0; j < 8; j++) acc[i][j] = 0.f;

    for (int k0 = 0; k0 < K; k0 += BKD) {
        #pragma unroll
        for (int i = 0; i < 2; i++) {
            int r = arow + i * 64;
            float4 v = *(const float4*)(A + (size_t)(bm + r) * K + k0 + acol);
            As[acol + 0][r] = v.x;
            As[acol + 1][r] = v.y;
            As[acol + 2][r] = v.z;
            As[acol + 3][r] = v.w;
        }
        #pragma unroll
        for (int i = 0; i < 2; i++) {
            int r = brow + i * 8;
            *(float4*)(&Bs[r][bcol]) =
                *(const float4*)(B + (size_t)(k0 + r) * N + bn + bcol);
        }
        __syncthreads();

        #pragma unroll
        for (int kk = 0; kk < BKD; kk++) {
            float4 a0 = *(float4*)(&As[kk][tr]);
            float4 a1 = *(float4*)(&As[kk][tr + 4]);
            float4 b0 = *(float4*)(&Bs[kk][tc]);
            float4 b1 = *(float4*)(&Bs[kk][tc + 4]);
            float ra[8] = {a0.x, a0.y, a0.z, a0.w, a1.x, a1.y, a1.z, a1.w};
            float rb[8] = {b0.x, b0.y, b0.z, b0.w, b1.x, b1.y, b1.z, b1.w};
            #pragma unroll
            for (int i = 0; i < 8; i++)
                #pragma unroll
                for (int j = 0; j < 8; j++)
                    acc[i][j] += ra[i] * rb[j];
        }
        __syncthreads();
    }

    #pragma unroll
    for (int i = 0; i < 8; i++) {
        #pragma unroll
        for (int j = 0; j < 8; j += 4) {
            float4 o;
            o.x = acc[i][j + 0] + bias[bn + tc + j + 0];
            o.y = acc[i][j + 1] + bias[bn + tc + j + 1];
            o.z = acc[i][j + 2] + bias[bn + tc + j + 2];
            o.w = acc[i][j + 3] + bias[bn + tc + j + 3];
            *(float4*)(C + (size_t)(bm + tr + i) * N + bn + tc + j) = o;
        }
    }
}

// ---------------- RoPE table (fp64 angle, rounded to f32 like numpy) ----------------
__global__ void rope_table()
{
    int idx = blockIdx.x * blockDim.x + threadIdx.x;
    if (idx >= SEQ * HD) return;
    int t = idx / HD;
    int j = idx % HD;
    int m = j & 31;  // j % 32
    double inv = exp(-((double)m / 32.0) * log(100000.0));
    // numpy computes angle in f64, casts to f32 BEFORE trig
    float af = (float)((double)t * inv);
    double s, c;
    sincos((double)af, &s, &c);
    g_cos[idx] = (float)c;
    g_sin[idx] = (float)s;
}

// ---------------- RoPE apply (interleaved rotate, concat cos/sin) ----------------
__global__ void rope_apply(float* __restrict__ X, int nheads)
{
    int idx = blockIdx.x * blockDim.x + threadIdx.x;
    int total = MROWS * nheads * 32;
    if (idx >= total) return;
    int pair = idx & 31;        // 0..31
    int tmp  = idx >> 5;
    int head = tmp % nheads;
    int row  = tmp / nheads;
    int t = row & (SEQ - 1);    // row = b*SEQ + s
    float* p = X + (size_t)row * nheads * HD + head * HD + pair * 2;
    float x0 = p[0], x1 = p[1];
    int j0 = pair * 2, j1 = pair * 2 + 1;
    float c0 = g_cos[t * HD + j0], s0 = g_sin[t * HD + j0];
    float c1 = g_cos[t * HD + j1], s1 = g_sin[t * HD + j1];
    p[0] = x0 * c0 - x1 * s0;
    p[1] = x1 * c1 + x0 * s1;
}

// ---------------- flash attention (fp32, causal, GQA) ----------------
#define QT 64
#define KT 64
#define PADR 65
// smem floats: Qst 64*65 + Kst 64*65 + Vs 64*64 + Ps 64*65 + m 64 + l 64 + kmask 64
#define ATTN_SMEM_FLOATS (3*64*PADR + 64*64 + 3*64)
#define ATTN_SMEM_BYTES  (ATTN_SMEM_FLOATS * 4)

__global__ __launch_bounds__(256)
void attn_kernel(const float* __restrict__ Q, const float* __restrict__ K,
                 const float* __restrict__ V, const int* __restrict__ mask,
                 float* __restrict__ O)
{
    extern __shared__ float sm[];
    float* Qst  = sm;                       // [d][r], pad 65
    float* Kst  = Qst + 64 * PADR;          // [d][c], pad 65
    float* Vs   = Kst + 64 * PADR;          // [c][d], natural
    float* Ps   = Vs + 64 * 64;             // [r][c], pad 65
    float* mrow = Ps + 64 * PADR;
    float* lrow = mrow + 64;
    float* kms  = lrow + 64;

    int tid = threadIdx.x;
    int qt = blockIdx.x, h = blockIdx.y, b = blockIdx.z;
    int kv = h >> 2;   // 16 heads -> 4 kv heads

    // load Q tile (transposed into smem)
    for (int i = tid; i < 64 * 16; i += 256) {
        int r = i >> 4;
        int f = (i & 15) * 4;
        float4 v = *(const float4*)(Q + ((size_t)b * SEQ + qt * QT + r) * HIDDEN + h * HD + f);
        Qst[(f + 0) * PADR + r] = v.x;
        Qst[(f + 1) * PADR + r] = v.y;
        Qst[(f + 2) * PADR + r] = v.z;
        Qst[(f + 3) * PADR + r] = v.w;
    }
    if (tid < 64) { mrow[tid] = -1e30f; lrow[tid] = 0.f; }

    int trl = (tid >> 4) * 4;   // row base (0..60)
    int tcl = (tid & 15) * 4;   // col base (0..60)

    float oacc[4][4];
    #pragma unroll
    for (int i = 0; i < 4; i++)
        #pragma unroll
        for (int j = 0; j < 4; j++) oacc[i][j] = 0.f;

    for (int kt = 0; kt <= qt; kt++) {
        __syncthreads();   // ensure previous PV done before tile overwrite
        // load K (transposed) and V (natural)
        for (int i = tid; i < 64 * 16; i += 256) {
            int r = i >> 4;
            int f = (i & 15) * 4;
            size_t grow = (size_t)b * SEQ + kt * KT + r;
            float4 kvv = *(const float4*)(K + grow * KVW + kv * HD + f);
            Kst[(f + 0) * PADR + r] = kvv.x;
            Kst[(f + 1) * PADR + r] = kvv.y;
            Kst[(f + 2) * PADR + r] = kvv.z;
            Kst[(f + 3) * PADR + r] = kvv.w;
            *(float4*)(&Vs[r * 64 + f]) = *(const float4*)(V + grow * KVW + kv * HD + f);
        }
        if (tid < 64) kms[tid] = (float)mask[b * SEQ + kt * KT + tid];
        __syncthreads();

        // ---- scores: 4x4 microtile per thread ----
        float s4[4][4];
        #pragma unroll
        for (int i = 0; i < 4; i++)
            #pragma unroll
            for (int j = 0; j < 4; j++) s4[i][j] = 0.f;

        for (int d = 0; d < 64; d++) {
            float rq[4], rk[4];
            #pragma unroll
            for (int i = 0; i < 4; i++) rq[i] = Qst[d * PADR + trl + i];
            #pragma unroll
            for (int j = 0; j < 4; j++) rk[j] = Kst[d * PADR + tcl + j];
            #pragma unroll
            for (int i = 0; i < 4; i++)
                #pragma unroll
                for (int j = 0; j < 4; j++)
                    s4[i][j] += rq[i] * rk[j];
        }

        // ---- mask + scale + tile row max ----
        float mt[4];
        #pragma unroll
        for (int i = 0; i < 4; i++) {
            int rg = qt * QT + trl + i;
            mt[i] = -1e30f;
            #pragma unroll
            for (int j = 0; j < 4; j++) {
                int cg = kt * KT + tcl + j;
                float s = s4[i][j] * 0.125f;
                if (cg > rg || kms[tcl + j] == 0.f) s = -1e30f;
                s4[i][j] = s;
                mt[i] = fmaxf(mt[i], s);
            }
        }
        #pragma unroll
        for (int off = 8; off; off >>= 1)
            #pragma unroll
            for (int i = 0; i < 4; i++)
                mt[i] = fmaxf(mt[i], __shfl_xor_sync(0xffffffffu, mt[i], off));

        // ---- online softmax update ----
        float lsum[4];
        #pragma unroll
        for (int i = 0; i < 4; i++) {
            float mo = mrow[trl + i];
            float mn = fmaxf(mo, mt[i]);
            float scl = __expf(mo - mn);
            lsum[i] = 0.f;
            #pragma unroll
            for (int j = 0; j < 4; j++) {
                float e = __expf(s4[i][j] - mn);
                Ps[(trl + i) * PADR + tcl + j] = e;
                lsum[i] += e;
            }
            #pragma unroll
            for (int j = 0; j < 4; j++) oacc[i][j] *= scl;
            s4[i][0] = mn;   // stash
            s4[i][1] = scl;
        }
        #pragma unroll
        for (int off = 8; off; off >>= 1)
            #pragma unroll
            for (int i = 0; i < 4; i++)
                lsum[i] += __shfl_xor_sync(0xffffffffu, lsum[i], off);
        if ((tid & 15) == 0) {
            #pragma unroll
            for (int i = 0; i < 4; i++) {
                lrow[trl + i] = lrow[trl + i] * s4[i][1] + lsum[i];
                mrow[trl + i] = s4[i][0];
            }
        }
        __syncthreads();

        // ---- PV accumulate ----
        for (int c = 0; c < 64; c++) {
            float rp[4];
            #pragma unroll
            for (int i = 0; i < 4; i++) rp[i] = Ps[(trl + i) * PADR + c];
            float4 rv = *(float4*)(&Vs[c * 64 + tcl]);
            #pragma unroll
            for (int i = 0; i < 4; i++) {
                oacc[i][0] += rp[i] * rv.x;
                oacc[i][1] += rp[i] * rv.y;
                oacc[i][2] += rp[i] * rv.z;
                oacc[i][3] += rp[i] * rv.w;
            }
        }
    }
    __syncthreads();

    #pragma unroll
    for (int i = 0; i < 4; i++) {
        float inv_l = 1.f / lrow[trl + i];
        float4 o;
        o.x = oacc[i][0] * inv_l;
        o.y = oacc[i][1] * inv_l;
        o.z = oacc[i][2] * inv_l;
        o.w = oacc[i][3] * inv_l;
        *(float4*)(O + ((size_t)b * SEQ + qt * QT + trl + i) * HIDDEN + h * HD + tcl) = o;
    }
}

// ---------------- launcher ----------------
extern "C" void kernel_launch(void* const* d_in, const int* in_sizes, int n_in,
                              void* d_out, int out_size)
{
    const float* X  = (const float*)d_in[0];
    const int*   mk = (const int*)  d_in[1];
    const float* Wq = (const float*)d_in[2];
    const float* bq = (const float*)d_in[3];
    const float* Wk = (const float*)d_in[4];
    const float* bk = (const float*)d_in[5];
    const float* Wv = (const float*)d_in[6];
    const float* bv = (const float*)d_in[7];
    const float* Wo = (const float*)d_in[8];
    const float* bo = (const float*)d_in[9];
    float* out = (float*)d_out;

    float *qp, *kp, *vp, *ap;
    cudaGetSymbolAddress((void**)&qp, g_Q);
    cudaGetSymbolAddress((void**)&kp, g_K);
    cudaGetSymbolAddress((void**)&vp, g_V);
    cudaGetSymbolAddress((void**)&ap, g_attn);

    cudaFuncSetAttribute(attn_kernel, cudaFuncAttributeMaxDynamicSharedMemorySize,
                         ATTN_SMEM_BYTES);

    // projections
    sgemm_bias<<<dim3(HIDDEN / BN, MROWS / BM), 256>>>(X, Wq, bq, qp, MROWS, HIDDEN, HIDDEN);
    sgemm_bias<<<dim3(KVW / BN,    MROWS / BM), 256>>>(X, Wk, bk, kp, MROWS, KVW, HIDDEN);
    sgemm_bias<<<dim3(KVW / BN,    MROWS / BM), 256>>>(X, Wv, bv, vp, MROWS, KVW, HIDDEN);

    // RoPE
    rope_table<<<(SEQ * HD + 255) / 256, 256>>>();
    rope_apply<<<((size_t)MROWS * NHEADS * 32 + 255) / 256, 256>>>(qp, NHEADS);
    rope_apply<<<((size_t)MROWS * NKV    * 32 + 255) / 256, 256>>>(kp, NKV);

    // attention
    attn_kernel<<<dim3(SEQ / QT, NHEADS, BATCH), 256, ATTN_SMEM_BYTES>>>(qp, kp, vp, mk, ap);

    // output projection
    sgemm_bias<<<dim3(HIDDEN / BN, MROWS / BM), 256>>>(ap, Wo, bo, out, MROWS, HIDDEN, HIDDEN);
}

// round 3
// speedup vs baseline: 1.4289x; 1.4289x over previous
#include <cuda_runtime.h>
#include <cuda_bf16.h>
#include <math.h>
#include <stdint.h>

#define HIDDEN 1024
#define NHEADS 16
#define NKV 4
#define HD 64
#define BATCH 2
#define SEQ 2048
#define MROWS (BATCH*SEQ)     // 4096
#define KVW (NKV*HD)          // 256

// ---------------- scratch (no allocations allowed) ----------------
__device__ float g_Q[(size_t)MROWS*HIDDEN];
__device__ float g_K[(size_t)MROWS*KVW];
__device__ float g_V[(size_t)MROWS*KVW];
__device__ float g_attn[(size_t)MROWS*HIDDEN];
__device__ float g_cos[SEQ*HD];
__device__ float g_sin[SEQ*HD];

// bf16 hi/lo split buffers
__device__ __nv_bfloat16 g_X0[(size_t)MROWS*HIDDEN];
__device__ __nv_bfloat16 g_X1[(size_t)MROWS*HIDDEN];
__device__ __nv_bfloat16 g_Wq0[(size_t)HIDDEN*HIDDEN];
__device__ __nv_bfloat16 g_Wq1[(size_t)HIDDEN*HIDDEN];
__device__ __nv_bfloat16 g_Wk0[(size_t)KVW*HIDDEN];
__device__ __nv_bfloat16 g_Wk1[(size_t)KVW*HIDDEN];
__device__ __nv_bfloat16 g_Wv0[(size_t)KVW*HIDDEN];
__device__ __nv_bfloat16 g_Wv1[(size_t)KVW*HIDDEN];
__device__ __nv_bfloat16 g_Wo0[(size_t)HIDDEN*HIDDEN];
__device__ __nv_bfloat16 g_Wo1[(size_t)HIDDEN*HIDDEN];

// ================= small PTX helpers (sm_80-era, no 'a' features) =================
__device__ __forceinline__ void cp_async16(uint32_t saddr, const void* gaddr) {
    asm volatile("cp.async.ca.shared.global [%0], [%1], 16;"
                 :: "r"(saddr), "l"(gaddr));
}
__device__ __forceinline__ void cp_commit() {
    asm volatile("cp.async.commit_group;");
}
__device__ __forceinline__ void cp_wait0() {
    asm volatile("cp.async.wait_group 0;");
}
__device__ __forceinline__ void ldsm_x4(uint32_t* r, uint32_t addr) {
    asm volatile("ldmatrix.sync.aligned.m8n8.x4.shared.b16 {%0,%1,%2,%3}, [%4];"
                 : "=r"(r[0]), "=r"(r[1]), "=r"(r[2]), "=r"(r[3]) : "r"(addr));
}
__device__ __forceinline__ void mma_bf16(float* c, const uint32_t* a, const uint32_t* b) {
    asm volatile("mma.sync.aligned.m16n8k16.row.col.f32.bf16.bf16.f32 "
                 "{%0,%1,%2,%3}, {%4,%5,%6,%7}, {%8,%9}, {%0,%1,%2,%3};"
                 : "+f"(c[0]), "+f"(c[1]), "+f"(c[2]), "+f"(c[3])
                 : "r"(a[0]), "r"(a[1]), "r"(a[2]), "r"(a[3]),
                   "r"(b[0]), "r"(b[1]));
}

// ================= prep kernels =================

// fp32 -> bf16 hi/lo split, vectorized by 4
__global__ void split_kernel(const float* __restrict__ X, __nv_bfloat16* __restrict__ H,
                             __nv_bfloat16* __restrict__ L, int n4)
{
    int i = blockIdx.x * blockDim.x + threadIdx.x;
    if (i >= n4) return;
    float4 v = ((const float4*)X)[i];
    float f[4] = {v.x, v.y, v.z, v.w};
    __nv_bfloat16 h[4], l[4];
    #pragma unroll
    for (int j = 0; j < 4; j++) {
        h[j] = __float2bfloat16(f[j]);
        l[j] = __float2bfloat16(f[j] - __bfloat162float(h[j]));
    }
    __nv_bfloat162* H2 = (__nv_bfloat162*)H;
    __nv_bfloat162* L2 = (__nv_bfloat162*)L;
    H2[2*i+0] = __nv_bfloat162{h[0], h[1]};
    H2[2*i+1] = __nv_bfloat162{h[2], h[3]};
    L2[2*i+0] = __nv_bfloat162{l[0], l[1]};
    L2[2*i+1] = __nv_bfloat162{l[2], l[3]};
}

// W[K,N] fp32 -> Wt hi/lo bf16 [N,K]
__global__ void wtrans_kernel(const float* __restrict__ W, __nv_bfloat16* __restrict__ H,
                              __nv_bfloat16* __restrict__ L, int K, int N)
{
    __shared__ float t[32][33];
    int nb = blockIdx.x * 32, kb = blockIdx.y * 32;
    int tx = threadIdx.x, ty = threadIdx.y;   // 32 x 8
    #pragma unroll
    for (int r = 0; r < 32; r += 8)
        t[ty + r][tx] = W[(size_t)(kb + ty + r) * N + nb + tx];
    __syncthreads();
    #pragma unroll
    for (int r = 0; r < 32; r += 8) {
        float v = t[tx][ty + r];
        __nv_bfloat16 h = __float2bfloat16(v);
        size_t o = (size_t)(nb + ty + r) * K + kb + tx;
        H[o] = h;
        L[o] = __float2bfloat16(v - __bfloat162float(h));
    }
}

// ================= HMMA bf16x3 GEMM: C = A[MxK] @ Wt^T + bias =================
// A0/A1: [M,K] hi/lo bf16.  B0/B1: [N,K] hi/lo bf16 (pre-transposed weights).
// Tile 128x128x32, 256 threads (8 warps in 2x4), warp tile 64x32.
#define GBM 128
#define GBN 128
#define GBK 32
#define APITCH 40                         // 32 + 8 pad bf16 (80B rows; conflict-free ldmatrix)
#define MAT_BYTES (GBM * APITCH * 2)      // 10240
#define STG_BYTES (4 * MAT_BYTES)         // A0 A1 B0 B1 = 40960
#define GEMM_SMEM (2 * STG_BYTES)         // 81920

__device__ __forceinline__ void gemm_stage_issue(
    uint32_t sb, const __nv_bfloat16* A0, const __nv_bfloat16* A1,
    const __nv_bfloat16* B0, const __nv_bfloat16* B1,
    int m0, int n0, int k0, int K, int tid)
{
    #pragma unroll
    for (int i = 0; i < 2; i++) {
        int idx = tid + i * 256;          // 512 chunks of 16B per matrix
        int r = idx >> 2, c = idx & 3;
        uint32_t so = (uint32_t)(r * 80 + c * 16);
        size_t goA = (size_t)(m0 + r) * K + k0 + c * 8;
        size_t goB = (size_t)(n0 + r) * K + k0 + c * 8;
        cp_async16(sb + 0 * MAT_BYTES + so, A0 + goA);
        cp_async16(sb + 1 * MAT_BYTES + so, A1 + goA);
        cp_async16(sb + 2 * MAT_BYTES + so, B0 + goB);
        cp_async16(sb + 3 * MAT_BYTES + so, B1 + goB);
    }
    cp_commit();
}

__global__ __launch_bounds__(256, 1)
void gemm_mma(const __nv_bfloat16* __restrict__ A0, const __nv_bfloat16* __restrict__ A1,
              const __nv_bfloat16* __restrict__ B0, const __nv_bfloat16* __restrict__ B1,
              const float* __restrict__ bias, float* __restrict__ C, int Ntot, int K)
{
    extern __shared__ char dsm[];
    uint32_t sbu = (uint32_t)__cvta_generic_to_shared(dsm);

    int tid = threadIdx.x;
    int wid = tid >> 5, lane = tid & 31;
    int wm = wid >> 2;          // 0..1 -> 64 rows each
    int wn = wid & 3;           // 0..3 -> 32 cols each
    int m0 = blockIdx.y * GBM, n0 = blockIdx.x * GBN;

    float acc[4][4][4];
    #pragma unroll
    for (int i = 0; i < 4; i++)
        #pragma unroll
        for (int j = 0; j < 4; j++)
            #pragma unroll
            for (int k = 0; k < 4; k++) acc[i][j][k] = 0.f;

    const int NIT = K / GBK;   // 32

    gemm_stage_issue(sbu, A0, A1, B0, B1, m0, n0, 0, K, tid);
    cp_wait0();
    __syncthreads();

    int s = 0;
    for (int it = 0; it < NIT; it++) {
        if (it + 1 < NIT)
            gemm_stage_issue(sbu + (s ^ 1) * STG_BYTES, A0, A1, B0, B1,
                             m0, n0, (it + 1) * GBK, K, tid);

        uint32_t base = sbu + s * STG_BYTES;
        // fragment smem addresses
        uint32_t aRow = (uint32_t)(wm * 64 + (lane & 15));
        uint32_t aColB = (uint32_t)((lane >> 4) * 16);           // bytes
        uint32_t bRow = (uint32_t)(wn * 32 + ((lane >> 4) * 8) + (lane & 7));
        uint32_t bColB = (uint32_t)(((lane >> 3) & 1) * 16);     // bytes

        #pragma unroll
        for (int kk = 0; kk < 2; kk++) {
            uint32_t kOffB = (uint32_t)(kk * 32);
            uint32_t a0f[4][4], a1f[4][4], b0f[4][2], b1f[4][2];
            #pragma unroll
            for (int mt = 0; mt < 4; mt++) {
                uint32_t ad = base + (aRow + mt * 16) * 80 + kOffB + aColB;
                ldsm_x4(a0f[mt], ad);
                ldsm_x4(a1f[mt], ad + MAT_BYTES);
            }
            #pragma unroll
            for (int nt2 = 0; nt2 < 2; nt2++) {
                uint32_t bd = base + 2 * MAT_BYTES + (bRow + nt2 * 16) * 80 + kOffB + bColB;
                uint32_t t0[4], t1[4];
                ldsm_x4(t0, bd);
                ldsm_x4(t1, bd + MAT_BYTES);
                b0f[nt2 * 2 + 0][0] = t0[0]; b0f[nt2 * 2 + 0][1] = t0[1];
                b0f[nt2 * 2 + 1][0] = t0[2]; b0f[nt2 * 2 + 1][1] = t0[3];
                b1f[nt2 * 2 + 0][0] = t1[0]; b1f[nt2 * 2 + 0][1] = t1[1];
                b1f[nt2 * 2 + 1][0] = t1[2]; b1f[nt2 * 2 + 1][1] = t1[3];
            }
            #pragma unroll
            for (int mt = 0; mt < 4; mt++)
                #pragma unroll
                for (int nt = 0; nt < 4; nt++) {
                    mma_bf16(acc[mt][nt], a0f[mt], b0f[nt]);
                    mma_bf16(acc[mt][nt], a0f[mt], b1f[nt]);
                    mma_bf16(acc[mt][nt], a1f[mt], b0f[nt]);
                }
        }
        if (it + 1 < NIT) cp_wait0();
        __syncthreads();
        s ^= 1;
    }

    // epilogue
    #pragma unroll
    for (int mt = 0; mt < 4; mt++) {
        int row0 = m0 + wm * 64 + mt * 16 + (lane >> 2);
        #pragma unroll
        for (int nt = 0; nt < 4; nt++) {
            int col = n0 + wn * 32 + nt * 8 + (lane & 3) * 2;
            float2 bb = *(const float2*)(bias + col);
            float2 o0 = {acc[mt][nt][0] + bb.x, acc[mt][nt][1] + bb.y};
            float2 o1 = {acc[mt][nt][2] + bb.x, acc[mt][nt][3] + bb.y};
            *(float2*)(C + (size_t)row0 * Ntot + col) = o0;
            *(float2*)(C + (size_t)(row0 + 8) * Ntot + col) = o1;
        }
    }
}

// ---------------- RoPE table (fp64 angle like numpy, float trig) ----------------
__global__ void rope_table()
{
    __shared__ double dinv[32];
    int tid = threadIdx.x;
    if (tid < 32) dinv[tid] = exp(-((double)tid / 32.0) * log(100000.0));
    __syncthreads();
    int idx = blockIdx.x * blockDim.x + tid;
    if (idx >= SEQ * HD) return;
    int t = idx >> 6;
    int j = idx & 63;
    int m = j & 31;
    float af = (float)((double)t * dinv[m]);  // f64 product, cast to f32 (matches numpy)
    float s, c;
    sincosf(af, &s, &c);
    g_cos[idx] = c;
    g_sin[idx] = s;
}

// ---------------- RoPE apply ----------------
__global__ void rope_apply(float* __restrict__ X, int nheads)
{
    int idx = blockIdx.x * blockDim.x + threadIdx.x;
    int total = MROWS * nheads * 32;
    if (idx >= total) return;
    int pair = idx & 31;
    int tmp  = idx >> 5;
    int head = tmp % nheads;
    int row  = tmp / nheads;
    int t = row & (SEQ - 1);
    float* p = X + (size_t)row * nheads * HD + head * HD + pair * 2;
    float x0 = p[0], x1 = p[1];
    int j0 = pair * 2, j1 = pair * 2 + 1;
    float c0 = g_cos[t * HD + j0], s0 = g_sin[t * HD + j0];
    float c1 = g_cos[t * HD + j1], s1 = g_sin[t * HD + j1];
    p[0] = x0 * c0 - x1 * s0;
    p[1] = x1 * c1 + x0 * s1;
}

// ---------------- flash attention (fp32, causal, GQA) ----------------
#define QT 64
#define KT 64
#define PADR 65
#define ATTN_SMEM_FLOATS (3*64*PADR + 64*64 + 3*64)
#define ATTN_SMEM_BYTES  (ATTN_SMEM_FLOATS * 4)

__global__ __launch_bounds__(256)
void attn_kernel(const float* __restrict__ Q, const float* __restrict__ K,
                 const float* __restrict__ V, const int* __restrict__ mask,
                 float* __restrict__ O)
{
    extern __shared__ float sm[];
    float* Qst  = sm;
    float* Kst  = Qst + 64 * PADR;
    float* Vs   = Kst + 64 * PADR;
    float* Ps   = Vs + 64 * 64;
    float* mrow = Ps + 64 * PADR;
    float* lrow = mrow + 64;
    float* kms  = lrow + 64;

    int tid = threadIdx.x;
    int qt = blockIdx.x, h = blockIdx.y, b = blockIdx.z;
    int kv = h >> 2;

    for (int i = tid; i < 64 * 16; i += 256) {
        int r = i >> 4;
        int f = (i & 15) * 4;
        float4 v = *(const float4*)(Q + ((size_t)b * SEQ + qt * QT + r) * HIDDEN + h * HD + f);
        Qst[(f + 0) * PADR + r] = v.x;
        Qst[(f + 1) * PADR + r] = v.y;
        Qst[(f + 2) * PADR + r] = v.z;
        Qst[(f + 3) * PADR + r] = v.w;
    }
    if (tid < 64) { mrow[tid] = -1e30f; lrow[tid] = 0.f; }

    int trl = (tid >> 4) * 4;
    int tcl = (tid & 15) * 4;

    float oacc[4][4];
    #pragma unroll
    for (int i = 0; i < 4; i++)
        #pragma unroll
        for (int j = 0; j < 4; j++) oacc[i][j] = 0.f;

    for (int kt = 0; kt <= qt; kt++) {
        __syncthreads();
        for (int i = tid; i < 64 * 16; i += 256) {
            int r = i >> 4;
            int f = (i & 15) * 4;
            size_t grow = (size_t)b * SEQ + kt * KT + r;
            float4 kvv = *(const float4*)(K + grow * KVW + kv * HD + f);
            Kst[(f + 0) * PADR + r] = kvv.x;
            Kst[(f + 1) * PADR + r] = kvv.y;
            Kst[(f + 2) * PADR + r] = kvv.z;
            Kst[(f + 3) * PADR + r] = kvv.w;
            *(float4*)(&Vs[r * 64 + f]) = *(const float4*)(V + grow * KVW + kv * HD + f);
        }
        if (tid < 64) kms[tid] = (float)mask[b * SEQ + kt * KT + tid];
        __syncthreads();

        float s4[4][4];
        #pragma unroll
        for (int i = 0; i < 4; i++)
            #pragma unroll
            for (int j = 0; j < 4; j++) s4[i][j] = 0.f;

        for (int d = 0; d < 64; d++) {
            float rq[4], rk[4];
            #pragma unroll
            for (int i = 0; i < 4; i++) rq[i] = Qst[d * PADR + trl + i];
            #pragma unroll
            for (int j = 0; j < 4; j++) rk[j] = Kst[d * PADR + tcl + j];
            #pragma unroll
            for (int i = 0; i < 4; i++)
                #pragma unroll
                for (int j = 0; j < 4; j++)
                    s4[i][j] += rq[i] * rk[j];
        }

        float mt[4];
        #pragma unroll
        for (int i = 0; i < 4; i++) {
            int rg = qt * QT + trl + i;
            mt[i] = -1e30f;
            #pragma unroll
            for (int j = 0; j < 4; j++) {
                int cg = kt * KT + tcl + j;
                float s = s4[i][j] * 0.125f;
                if (cg > rg || kms[tcl + j] == 0.f) s = -1e30f;
                s4[i][j] = s;
                mt[i] = fmaxf(mt[i], s);
            }
        }
        #pragma unroll
        for (int off = 8; off; off >>= 1)
            #pragma unroll
            for (int i = 0; i < 4; i++)
                mt[i] = fmaxf(mt[i], __shfl_xor_sync(0xffffffffu, mt[i], off));

        float lsum[4];
        #pragma unroll
        for (int i = 0; i < 4; i++) {
            float mo = mrow[trl + i];
            float mn = fmaxf(mo, mt[i]);
            float scl = __expf(mo - mn);
            lsum[i] = 0.f;
            #pragma unroll
            for (int j = 0; j < 4; j++) {
                float e = __expf(s4[i][j] - mn);
                Ps[(trl + i) * PADR + tcl + j] = e;
                lsum[i] += e;
            }
            #pragma unroll
            for (int j = 0; j < 4; j++) oacc[i][j] *= scl;
            s4[i][0] = mn;
            s4[i][1] = scl;
        }
        #pragma unroll
        for (int off = 8; off; off >>= 1)
            #pragma unroll
            for (int i = 0; i < 4; i++)
                lsum[i] += __shfl_xor_sync(0xffffffffu, lsum[i], off);
        if ((tid & 15) == 0) {
            #pragma unroll
            for (int i = 0; i < 4; i++) {
                lrow[trl + i] = lrow[trl + i] * s4[i][1] + lsum[i];
                mrow[trl + i] = s4[i][0];
            }
        }
        __syncthreads();

        for (int c = 0; c < 64; c++) {
            float rp[4];
            #pragma unroll
            for (int i = 0; i < 4; i++) rp[i] = Ps[(trl + i) * PADR + c];
            float4 rv = *(float4*)(&Vs[c * 64 + tcl]);
            #pragma unroll
            for (int i = 0; i < 4; i++) {
                oacc[i][0] += rp[i] * rv.x;
                oacc[i][1] += rp[i] * rv.y;
                oacc[i][2] += rp[i] * rv.z;
                oacc[i][3] += rp[i] * rv.w;
            }
        }
    }
    __syncthreads();

    #pragma unroll
    for (int i = 0; i < 4; i++) {
        float inv_l = 1.f / lrow[trl + i];
        float4 o;
        o.x = oacc[i][0] * inv_l;
        o.y = oacc[i][1] * inv_l;
        o.z = oacc[i][2] * inv_l;
        o.w = oacc[i][3] * inv_l;
        *(float4*)(O + ((size_t)b * SEQ + qt * QT + trl + i) * HIDDEN + h * HD + tcl) = o;
    }
}

// ---------------- launcher ----------------
extern "C" void kernel_launch(void* const* d_in, const int* in_sizes, int n_in,
                              void* d_out, int out_size)
{
    const float* X  = (const float*)d_in[0];
    const int*   mk = (const int*)  d_in[1];
    const float* Wq = (const float*)d_in[2];
    const float* bq = (const float*)d_in[3];
    const float* Wk = (const float*)d_in[4];
    const float* bk = (const float*)d_in[5];
    const float* Wv = (const float*)d_in[6];
    const float* bv = (const float*)d_in[7];
    const float* Wo = (const float*)d_in[8];
    const float* bo = (const float*)d_in[9];
    float* out = (float*)d_out;

    float *qp, *kp, *vp, *ap;
    cudaGetSymbolAddress((void**)&qp, g_Q);
    cudaGetSymbolAddress((void**)&kp, g_K);
    cudaGetSymbolAddress((void**)&vp, g_V);
    cudaGetSymbolAddress((void**)&ap, g_attn);

    __nv_bfloat16 *x0, *x1, *wq0, *wq1, *wk0, *wk1, *wv0, *wv1, *wo0, *wo1;
    cudaGetSymbolAddress((void**)&x0, g_X0);
    cudaGetSymbolAddress((void**)&x1, g_X1);
    cudaGetSymbolAddress((void**)&wq0, g_Wq0);
    cudaGetSymbolAddress((void**)&wq1, g_Wq1);
    cudaGetSymbolAddress((void**)&wk0, g_Wk0);
    cudaGetSymbolAddress((void**)&wk1, g_Wk1);
    cudaGetSymbolAddress((void**)&wv0, g_Wv0);
    cudaGetSymbolAddress((void**)&wv1, g_Wv1);
    cudaGetSymbolAddress((void**)&wo0, g_Wo0);
    cudaGetSymbolAddress((void**)&wo1, g_Wo1);

    cudaFuncSetAttribute(attn_kernel, cudaFuncAttributeMaxDynamicSharedMemorySize,
                         ATTN_SMEM_BYTES);
    cudaFuncSetAttribute(gemm_mma, cudaFuncAttributeMaxDynamicSharedMemorySize,
                         GEMM_SMEM);

    // weight transposes + splits
    wtrans_kernel<<<dim3(HIDDEN/32, HIDDEN/32), dim3(32,8)>>>(Wq, wq0, wq1, HIDDEN, HIDDEN);
    wtrans_kernel<<<dim3(KVW/32,    HIDDEN/32), dim3(32,8)>>>(Wk, wk0, wk1, HIDDEN, KVW);
    wtrans_kernel<<<dim3(KVW/32,    HIDDEN/32), dim3(32,8)>>>(Wv, wv0, wv1, HIDDEN, KVW);
    wtrans_kernel<<<dim3(HIDDEN/32, HIDDEN/32), dim3(32,8)>>>(Wo, wo0, wo1, HIDDEN, HIDDEN);

    // split input activations
    {
        int n4 = MROWS * HIDDEN / 4;
        split_kernel<<<(n4 + 255) / 256, 256>>>(X, x0, x1, n4);
    }

    // projections (HMMA bf16x3)
    gemm_mma<<<dim3(HIDDEN/GBN, MROWS/GBM), 256, GEMM_SMEM>>>(x0, x1, wq0, wq1, bq, qp, HIDDEN, HIDDEN);
    gemm_mma<<<dim3(KVW/GBN,    MROWS/GBM), 256, GEMM_SMEM>>>(x0, x1, wk0, wk1, bk, kp, KVW, HIDDEN);
    gemm_mma<<<dim3(KVW/GBN,    MROWS/GBM), 256, GEMM_SMEM>>>(x0, x1, wv0, wv1, bv, vp, KVW, HIDDEN);

    // RoPE
    rope_table<<<(SEQ * HD + 255) / 256, 256>>>();
    rope_apply<<<((size_t)MROWS * NHEADS * 32 + 255) / 256, 256>>>(qp, NHEADS);
    rope_apply<<<((size_t)MROWS * NKV    * 32 + 255) / 256, 256>>>(kp, NKV);

    // attention
    attn_kernel<<<dim3(SEQ / QT, NHEADS, BATCH), 256, ATTN_SMEM_BYTES>>>(qp, kp, vp, mk, ap);

    // split attention output, then output projection
    {
        int n4 = MROWS * HIDDEN / 4;
        split_kernel<<<(n4 + 255) / 256, 256>>>(ap, x0, x1, n4);
    }
    gemm_mma<<<dim3(HIDDEN/GBN, MROWS/GBM), 256, GEMM_SMEM>>>(x0, x1, wo0, wo1, bo, out, HIDDEN, HIDDEN);
}

// round 4
// speedup vs baseline: 2.5608x; 1.7921x over previous
#include <cuda_runtime.h>
#include <cuda_bf16.h>
#include <math.h>
#include <stdint.h>

#define HIDDEN 1024
#define NHEADS 16
#define NKV 4
#define HD 64
#define BATCH 2
#define SEQ 2048
#define MROWS (BATCH*SEQ)     // 4096
#define KVW (NKV*HD)          // 256

// ---------------- scratch (no allocations allowed) ----------------
__device__ float g_Q[(size_t)MROWS*HIDDEN];
__device__ float g_K[(size_t)MROWS*KVW];
__device__ float g_V[(size_t)MROWS*KVW];
__device__ float g_cos[SEQ*HD];
__device__ float g_sin[SEQ*HD];

// bf16 hi/lo split buffers
__device__ __align__(16) __nv_bfloat16 g_X0[(size_t)MROWS*HIDDEN];
__device__ __align__(16) __nv_bfloat16 g_X1[(size_t)MROWS*HIDDEN];
__device__ __align__(16) __nv_bfloat16 g_Wq0[(size_t)HIDDEN*HIDDEN];
__device__ __align__(16) __nv_bfloat16 g_Wq1[(size_t)HIDDEN*HIDDEN];
__device__ __align__(16) __nv_bfloat16 g_Wk0[(size_t)KVW*HIDDEN];
__device__ __align__(16) __nv_bfloat16 g_Wk1[(size_t)KVW*HIDDEN];
__device__ __align__(16) __nv_bfloat16 g_Wv0[(size_t)KVW*HIDDEN];
__device__ __align__(16) __nv_bfloat16 g_Wv1[(size_t)KVW*HIDDEN];
__device__ __align__(16) __nv_bfloat16 g_Wo0[(size_t)HIDDEN*HIDDEN];
__device__ __align__(16) __nv_bfloat16 g_Wo1[(size_t)HIDDEN*HIDDEN];
// attention operand buffers (bf16 hi/lo)
__device__ __align__(16) __nv_bfloat16 g_Qh[(size_t)MROWS*HIDDEN];
__device__ __align__(16) __nv_bfloat16 g_Ql[(size_t)MROWS*HIDDEN];
__device__ __align__(16) __nv_bfloat16 g_Kh[(size_t)MROWS*KVW];
__device__ __align__(16) __nv_bfloat16 g_Kl[(size_t)MROWS*KVW];
__device__ __align__(16) __nv_bfloat16 g_Vth[(size_t)MROWS*KVW];  // [b][kv][hd][seq]
__device__ __align__(16) __nv_bfloat16 g_Vtl[(size_t)MROWS*KVW];

// ================= small PTX helpers (sm_80-era, no 'a' features) =================
__device__ __forceinline__ void cp_async16(uint32_t saddr, const void* gaddr) {
    asm volatile("cp.async.ca.shared.global [%0], [%1], 16;"
                 :: "r"(saddr), "l"(gaddr));
}
__device__ __forceinline__ void cp_commit() {
    asm volatile("cp.async.commit_group;");
}
__device__ __forceinline__ void cp_wait0() {
    asm volatile("cp.async.wait_group 0;");
}
__device__ __forceinline__ void cp_wait1() {
    asm volatile("cp.async.wait_group 1;");
}
__device__ __forceinline__ void ldsm_x4(uint32_t* r, uint32_t addr) {
    asm volatile("ldmatrix.sync.aligned.m8n8.x4.shared.b16 {%0,%1,%2,%3}, [%4];"
                 : "=r"(r[0]), "=r"(r[1]), "=r"(r[2]), "=r"(r[3]) : "r"(addr));
}
__device__ __forceinline__ void mma_bf16(float* c, const uint32_t* a, const uint32_t* b) {
    asm volatile("mma.sync.aligned.m16n8k16.row.col.f32.bf16.bf16.f32 "
                 "{%0,%1,%2,%3}, {%4,%5,%6,%7}, {%8,%9}, {%0,%1,%2,%3};"
                 : "+f"(c[0]), "+f"(c[1]), "+f"(c[2]), "+f"(c[3])
                 : "r"(a[0]), "r"(a[1]), "r"(a[2]), "r"(a[3]),
                   "r"(b[0]), "r"(b[1]));
}
// split (x,y) fp32 into packed bf16 hi pair + lo (residual) pair
__device__ __forceinline__ void split2(float x, float y, uint32_t& hi, uint32_t& lo) {
    __nv_bfloat162 h = __floats2bfloat162_rn(x, y);
    float rx = x - __bfloat162float(h.x);
    float ry = y - __bfloat162float(h.y);
    __nv_bfloat162 l = __floats2bfloat162_rn(rx, ry);
    hi = *reinterpret_cast<uint32_t*>(&h);
    lo = *reinterpret_cast<uint32_t*>(&l);
}

// ================= prep kernels =================

// fp32 -> bf16 hi/lo split, vectorized by 4
__global__ void split_kernel(const float* __restrict__ X, __nv_bfloat16* __restrict__ H,
                             __nv_bfloat16* __restrict__ L, int n4)
{
    int i = blockIdx.x * blockDim.x + threadIdx.x;
    if (i >= n4) return;
    float4 v = ((const float4*)X)[i];
    float f[4] = {v.x, v.y, v.z, v.w};
    __nv_bfloat16 h[4], l[4];
    #pragma unroll
    for (int j = 0; j < 4; j++) {
        h[j] = __float2bfloat16(f[j]);
        l[j] = __float2bfloat16(f[j] - __bfloat162float(h[j]));
    }
    __nv_bfloat162* H2 = (__nv_bfloat162*)H;
    __nv_bfloat162* L2 = (__nv_bfloat162*)L;
    H2[2*i+0] = __nv_bfloat162{h[0], h[1]};
    H2[2*i+1] = __nv_bfloat162{h[2], h[3]};
    L2[2*i+0] = __nv_bfloat162{l[0], l[1]};
    L2[2*i+1] = __nv_bfloat162{l[2], l[3]};
}

// W[K,N] fp32 -> Wt hi/lo bf16 [N,K]
__global__ void wtrans_kernel(const float* __restrict__ W, __nv_bfloat16* __restrict__ H,
                              __nv_bfloat16* __restrict__ L, int K, int N)
{
    __shared__ float t[32][33];
    int nb = blockIdx.x * 32, kb = blockIdx.y * 32;
    int tx = threadIdx.x, ty = threadIdx.y;   // 32 x 8
    #pragma unroll
    for (int r = 0; r < 32; r += 8)
        t[ty + r][tx] = W[(size_t)(kb + ty + r) * N + nb + tx];
    __syncthreads();
    #pragma unroll
    for (int r = 0; r < 32; r += 8) {
        float v = t[tx][ty + r];
        __nv_bfloat16 h = __float2bfloat16(v);
        size_t o = (size_t)(nb + ty + r) * K + kb + tx;
        H[o] = h;
        L[o] = __float2bfloat16(v - __bfloat162float(h));
    }
}

// ================= HMMA bf16x3 GEMM (same as R3) =================
#define GBM 128
#define GBN 128
#define GBK 32
#define MAT_BYTES (GBM * 40 * 2)          // 10240 (pitch 40 bf16 = 80B)
#define STG_BYTES (4 * MAT_BYTES)
#define GEMM_SMEM (2 * STG_BYTES)

__device__ __forceinline__ void gemm_stage_issue(
    uint32_t sb, const __nv_bfloat16* A0, const __nv_bfloat16* A1,
    const __nv_bfloat16* B0, const __nv_bfloat16* B1,
    int m0, int n0, int k0, int K, int tid)
{
    #pragma unroll
    for (int i = 0; i < 2; i++) {
        int idx = tid + i * 256;
        int r = idx >> 2, c = idx & 3;
        uint32_t so = (uint32_t)(r * 80 + c * 16);
        size_t goA = (size_t)(m0 + r) * K + k0 + c * 8;
        size_t goB = (size_t)(n0 + r) * K + k0 + c * 8;
        cp_async16(sb + 0 * MAT_BYTES + so, A0 + goA);
        cp_async16(sb + 1 * MAT_BYTES + so, A1 + goA);
        cp_async16(sb + 2 * MAT_BYTES + so, B0 + goB);
        cp_async16(sb + 3 * MAT_BYTES + so, B1 + goB);
    }
    cp_commit();
}

__global__ __launch_bounds__(256, 1)
void gemm_mma(const __nv_bfloat16* __restrict__ A0, const __nv_bfloat16* __restrict__ A1,
              const __nv_bfloat16* __restrict__ B0, const __nv_bfloat16* __restrict__ B1,
              const float* __restrict__ bias, float* __restrict__ C, int Ntot, int K)
{
    extern __shared__ char dsm[];
    uint32_t sbu = (uint32_t)__cvta_generic_to_shared(dsm);

    int tid = threadIdx.x;
    int wid = tid >> 5, lane = tid & 31;
    int wm = wid >> 2;
    int wn = wid & 3;
    int m0 = blockIdx.y * GBM, n0 = blockIdx.x * GBN;

    float acc[4][4][4];
    #pragma unroll
    for (int i = 0; i < 4; i++)
        #pragma unroll
        for (int j = 0; j < 4; j++)
            #pragma unroll
            for (int k = 0; k < 4; k++) acc[i][j][k] = 0.f;

    const int NIT = K / GBK;

    gemm_stage_issue(sbu, A0, A1, B0, B1, m0, n0, 0, K, tid);
    cp_wait0();
    __syncthreads();

    int s = 0;
    for (int it = 0; it < NIT; it++) {
        if (it + 1 < NIT)
            gemm_stage_issue(sbu + (s ^ 1) * STG_BYTES, A0, A1, B0, B1,
                             m0, n0, (it + 1) * GBK, K, tid);

        uint32_t base = sbu + s * STG_BYTES;
        uint32_t aRow = (uint32_t)(wm * 64 + (lane & 15));
        uint32_t aColB = (uint32_t)((lane >> 4) * 16);
        uint32_t bRow = (uint32_t)(wn * 32 + ((lane >> 4) * 8) + (lane & 7));
        uint32_t bColB = (uint32_t)(((lane >> 3) & 1) * 16);

        #pragma unroll
        for (int kk = 0; kk < 2; kk++) {
            uint32_t kOffB = (uint32_t)(kk * 32);
            uint32_t a0f[4][4], a1f[4][4], b0f[4][2], b1f[4][2];
            #pragma unroll
            for (int mt = 0; mt < 4; mt++) {
                uint32_t ad = base + (aRow + mt * 16) * 80 + kOffB + aColB;
                ldsm_x4(a0f[mt], ad);
                ldsm_x4(a1f[mt], ad + MAT_BYTES);
            }
            #pragma unroll
            for (int nt2 = 0; nt2 < 2; nt2++) {
                uint32_t bd = base + 2 * MAT_BYTES + (bRow + nt2 * 16) * 80 + kOffB + bColB;
                uint32_t t0[4], t1[4];
                ldsm_x4(t0, bd);
                ldsm_x4(t1, bd + MAT_BYTES);
                b0f[nt2 * 2 + 0][0] = t0[0]; b0f[nt2 * 2 + 0][1] = t0[1];
                b0f[nt2 * 2 + 1][0] = t0[2]; b0f[nt2 * 2 + 1][1] = t0[3];
                b1f[nt2 * 2 + 0][0] = t1[0]; b1f[nt2 * 2 + 0][1] = t1[1];
                b1f[nt2 * 2 + 1][0] = t1[2]; b1f[nt2 * 2 + 1][1] = t1[3];
            }
            #pragma unroll
            for (int mt = 0; mt < 4; mt++)
                #pragma unroll
                for (int nt = 0; nt < 4; nt++) {
                    mma_bf16(acc[mt][nt], a0f[mt], b0f[nt]);
                    mma_bf16(acc[mt][nt], a0f[mt], b1f[nt]);
                    mma_bf16(acc[mt][nt], a1f[mt], b0f[nt]);
                }
        }
        if (it + 1 < NIT) cp_wait0();
        __syncthreads();
        s ^= 1;
    }

    #pragma unroll
    for (int mt = 0; mt < 4; mt++) {
        int row0 = m0 + wm * 64 + mt * 16 + (lane >> 2);
        #pragma unroll
        for (int nt = 0; nt < 4; nt++) {
            int col = n0 + wn * 32 + nt * 8 + (lane & 3) * 2;
            float2 bb = *(const float2*)(bias + col);
            float2 o0 = {acc[mt][nt][0] + bb.x, acc[mt][nt][1] + bb.y};
            float2 o1 = {acc[mt][nt][2] + bb.x, acc[mt][nt][3] + bb.y};
            *(float2*)(C + (size_t)row0 * Ntot + col) = o0;
            *(float2*)(C + (size_t)(row0 + 8) * Ntot + col) = o1;
        }
    }
}

// ---------------- RoPE table (fp64 angle like numpy, float trig) ----------------
__global__ void rope_table()
{
    __shared__ double dinv[32];
    int tid = threadIdx.x;
    if (tid < 32) dinv[tid] = exp(-((double)tid / 32.0) * log(100000.0));
    __syncthreads();
    int idx = blockIdx.x * blockDim.x + tid;
    if (idx >= SEQ * HD) return;
    int t = idx >> 6;
    int j = idx & 63;
    int m = j & 31;
    float af = (float)((double)t * dinv[m]);
    float s, c;
    sincosf(af, &s, &c);
    g_cos[idx] = c;
    g_sin[idx] = s;
}

// ---------------- RoPE apply + split to bf16 hi/lo ----------------
__global__ void rope_split(const float* __restrict__ X, __nv_bfloat16* __restrict__ H,
                           __nv_bfloat16* __restrict__ L, int nheads)
{
    int idx = blockIdx.x * blockDim.x + threadIdx.x;
    int total = MROWS * nheads * 32;
    if (idx >= total) return;
    int pair = idx & 31;
    int tmp  = idx >> 5;
    int head = tmp % nheads;
    int row  = tmp / nheads;
    int t = row & (SEQ - 1);
    size_t off = (size_t)row * nheads * HD + head * HD + pair * 2;
    const float* p = X + off;
    float x0 = p[0], x1 = p[1];
    int j0 = pair * 2, j1 = pair * 2 + 1;
    float c0 = g_cos[t * HD + j0], s0 = g_sin[t * HD + j0];
    float c1 = g_cos[t * HD + j1], s1 = g_sin[t * HD + j1];
    float r0 = x0 * c0 - x1 * s0;
    float r1 = x1 * c1 + x0 * s1;
    uint32_t hi, lo;
    split2(r0, r1, hi, lo);
    *(uint32_t*)(H + off) = hi;
    *(uint32_t*)(L + off) = lo;
}

// ---------------- V: split + transpose to [b][kv][hd][seq] ----------------
__global__ void vsplit_t(const float* __restrict__ V, __nv_bfloat16* __restrict__ H,
                         __nv_bfloat16* __restrict__ L)
{
    __shared__ float t[32][33];
    int s0 = blockIdx.x * 32;          // seq tile
    int c0 = blockIdx.y * 32;          // hd tile
    int bkv = blockIdx.z;              // b*4 + kv
    int b = bkv >> 2, kv = bkv & 3;
    int tx = threadIdx.x, ty = threadIdx.y;   // 32 x 8
    #pragma unroll
    for (int r = 0; r < 32; r += 8)
        t[ty + r][tx] = V[((size_t)(b * SEQ + s0 + ty + r) * NKV + kv) * HD + c0 + tx];
    __syncthreads();
    #pragma unroll
    for (int r = 0; r < 32; r += 8) {
        float v = t[tx][ty + r];   // seq = s0+tx, hd = c0+ty+r
        __nv_bfloat16 h = __float2bfloat16(v);
        size_t o = ((size_t)(b * NKV + kv) * HD + c0 + ty + r) * SEQ + s0 + tx;
        H[o] = h;
        L[o] = __float2bfloat16(v - __bfloat162float(h));
    }
}

// ================= HMMA flash attention (bf16x3, causal, GQA) =================
// CTA: 128 q rows x full kv loop in 64-col tiles. 8 warps x 16 rows.
// smem: Qh/Ql 128x72 bf16; per stage Kh/Kl/Vh/Vl 64x72 bf16; 2 stages; mask 2x64 f32.
#define AMAT 9216                 // 64*144 bytes
#define ASTG (4*AMAT)             // 36864
#define AQ_BYTES 36864            // 2 * 128*144
#define AMASK_OFF (AQ_BYTES + 2*ASTG)       // 110592
#define ATTN_SMEM (AMASK_OFF + 512)

__device__ __forceinline__ void attn_issue_kv(
    uint32_t sbuf, const __nv_bfloat16* Kh, const __nv_bfloat16* Kl,
    const __nv_bfloat16* Vh, const __nv_bfloat16* Vl,
    int b, int kv, int it, int tid)
{
    #pragma unroll
    for (int i = 0; i < 8; i++) {
        int c = tid + i * 256;
        int m = c >> 9;            // 0..3 : Kh,Kl,Vh,Vl
        int r = (c >> 3) & 63;
        int col = c & 7;
        const __nv_bfloat16* src;
        if (m == 0)      src = Kh + ((size_t)(b * SEQ + it * 64 + r) * NKV + kv) * HD + col * 8;
        else if (m == 1) src = Kl + ((size_t)(b * SEQ + it * 64 + r) * NKV + kv) * HD + col * 8;
        else if (m == 2) src = Vh + ((size_t)(b * NKV + kv) * HD + r) * SEQ + it * 64 + col * 8;
        else             src = Vl + ((size_t)(b * NKV + kv) * HD + r) * SEQ + it * 64 + col * 8;
        cp_async16(sbuf + m * AMAT + r * 144 + col * 16, src);
    }
}

__global__ __launch_bounds__(256)
void attn_mma(const __nv_bfloat16* __restrict__ Qh, const __nv_bfloat16* __restrict__ Ql,
              const __nv_bfloat16* __restrict__ Kh, const __nv_bfloat16* __restrict__ Kl,
              const __nv_bfloat16* __restrict__ Vh, const __nv_bfloat16* __restrict__ Vl,
              const int* __restrict__ mask,
              __nv_bfloat16* __restrict__ Oh, __nv_bfloat16* __restrict__ Ol)
{
    extern __shared__ char smc[];
    uint32_t sb = (uint32_t)__cvta_generic_to_shared(smc);
    float* maskf = (float*)(smc + AMASK_OFF);

    int tid = threadIdx.x, w = tid >> 5, lane = tid & 31;
    int qb = blockIdx.x, h = blockIdx.y, b = blockIdx.z, kv = h >> 2;
    int niter = 2 * qb + 2;

    // Q tile load (hi+lo): 2048 16B chunks
    #pragma unroll
    for (int i = 0; i < 8; i++) {
        int c = tid + i * 256;
        int m = c >> 10;
        int r = (c >> 3) & 127;
        int col = c & 7;
        const __nv_bfloat16* src = (m ? Ql : Qh)
            + ((size_t)(b * SEQ + qb * 128 + r) * NHEADS + h) * HD + col * 8;
        cp_async16(sb + m * 18432 + r * 144 + col * 16, src);
    }
    attn_issue_kv(sb + AQ_BYTES, Kh, Kl, Vh, Vl, b, kv, 0, tid);
    if (tid < 64) maskf[tid] = (float)mask[b * SEQ + tid];
    cp_commit();

    uint32_t aoff = (uint32_t)((w * 16 + (lane & 15)) * 144 + (lane >> 4) * 16);
    uint32_t boff = (uint32_t)((lane & 15) * 144 + (lane >> 4) * 16);
    int rg0 = qb * 128 + w * 16 + (lane >> 2);
    int rg1 = rg0 + 8;

    float oacc[8][4];
    #pragma unroll
    for (int i = 0; i < 8; i++)
        #pragma unroll
        for (int j = 0; j < 4; j++) oacc[i][j] = 0.f;
    float m0 = -1e30f, m1 = -1e30f, l0 = 0.f, l1 = 0.f;

    for (int it = 0; it < niter; it++) {
        int s = it & 1;
        if (it + 1 < niter) {
            attn_issue_kv(sb + AQ_BYTES + (s ^ 1) * ASTG, Kh, Kl, Vh, Vl, b, kv, it + 1, tid);
            if (tid < 64) maskf[(s ^ 1) * 64 + tid] = (float)mask[b * SEQ + (it + 1) * 64 + tid];
            cp_commit();
            cp_wait1();
        } else {
            cp_wait0();
        }
        __syncthreads();

        // warp-uniform skip: all 16 rows of this warp causally masked?
        if (it * 64 <= qb * 128 + w * 16 + 15) {
            uint32_t stg = sb + AQ_BYTES + s * ASTG;
            float sacc[8][4];
            #pragma unroll
            for (int i = 0; i < 8; i++)
                #pragma unroll
                for (int j = 0; j < 4; j++) sacc[i][j] = 0.f;

            uint32_t qhB = sb + aoff, qlB = sb + 18432 + aoff;
            #pragma unroll
            for (int ks = 0; ks < 4; ks++) {
                uint32_t ah[4], al4[4];
                ldsm_x4(ah, qhB + ks * 32);
                ldsm_x4(al4, qlB + ks * 32);
                #pragma unroll
                for (int np = 0; np < 4; np++) {
                    uint32_t kh4[4], kl4[4];
                    uint32_t ka = stg + np * 2304 + boff + ks * 32;
                    ldsm_x4(kh4, ka);
                    ldsm_x4(kl4, ka + AMAT);
                    uint32_t bh0[2] = {kh4[0], kh4[2]}, bh1[2] = {kh4[1], kh4[3]};
                    uint32_t bl0[2] = {kl4[0], kl4[2]}, bl1[2] = {kl4[1], kl4[3]};
                    mma_bf16(sacc[2 * np], ah, bh0);
                    mma_bf16(sacc[2 * np], al4, bh0);
                    mma_bf16(sacc[2 * np], ah, bl0);
                    mma_bf16(sacc[2 * np + 1], ah, bh1);
                    mma_bf16(sacc[2 * np + 1], al4, bh1);
                    mma_bf16(sacc[2 * np + 1], ah, bl1);
                }
            }

            // mask + scale + row max
            const float* mk = maskf + s * 64;
            float mr0 = -1e30f, mr1 = -1e30f;
            #pragma unroll
            for (int nt = 0; nt < 8; nt++) {
                int cg = it * 64 + nt * 8 + (lane & 3) * 2;
                float km0 = mk[nt * 8 + (lane & 3) * 2];
                float km1 = mk[nt * 8 + (lane & 3) * 2 + 1];
                float v0 = sacc[nt][0] * 0.125f, v1 = sacc[nt][1] * 0.125f;
                float v2 = sacc[nt][2] * 0.125f, v3 = sacc[nt][3] * 0.125f;
                if (cg     > rg0 || km0 == 0.f) v0 = -1e30f;
                if (cg + 1 > rg0 || km1 == 0.f) v1 = -1e30f;
                if (cg     > rg1 || km0 == 0.f) v2 = -1e30f;
                if (cg + 1 > rg1 || km1 == 0.f) v3 = -1e30f;
                sacc[nt][0] = v0; sacc[nt][1] = v1; sacc[nt][2] = v2; sacc[nt][3] = v3;
                mr0 = fmaxf(mr0, fmaxf(v0, v1));
                mr1 = fmaxf(mr1, fmaxf(v2, v3));
            }
            mr0 = fmaxf(mr0, __shfl_xor_sync(0xffffffffu, mr0, 1));
            mr0 = fmaxf(mr0, __shfl_xor_sync(0xffffffffu, mr0, 2));
            mr1 = fmaxf(mr1, __shfl_xor_sync(0xffffffffu, mr1, 1));
            mr1 = fmaxf(mr1, __shfl_xor_sync(0xffffffffu, mr1, 2));

            float mn0 = fmaxf(m0, mr0), mn1 = fmaxf(m1, mr1);
            float sc0 = __expf(m0 - mn0), sc1 = __expf(m1 - mn1);
            float base0 = (mn0 < -5e29f) ? 0.f : mn0;
            float base1 = (mn1 < -5e29f) ? 0.f : mn1;
            m0 = mn0; m1 = mn1;

            float rs0 = 0.f, rs1 = 0.f;
            #pragma unroll
            for (int nt = 0; nt < 8; nt++) {
                float p0 = __expf(sacc[nt][0] - base0);
                float p1 = __expf(sacc[nt][1] - base0);
                float p2 = __expf(sacc[nt][2] - base1);
                float p3 = __expf(sacc[nt][3] - base1);
                sacc[nt][0] = p0; sacc[nt][1] = p1; sacc[nt][2] = p2; sacc[nt][3] = p3;
                rs0 += p0 + p1; rs1 += p2 + p3;
                oacc[nt][0] *= sc0; oacc[nt][1] *= sc0;
                oacc[nt][2] *= sc1; oacc[nt][3] *= sc1;
            }
            rs0 += __shfl_xor_sync(0xffffffffu, rs0, 1);
            rs0 += __shfl_xor_sync(0xffffffffu, rs0, 2);
            rs1 += __shfl_xor_sync(0xffffffffu, rs1, 1);
            rs1 += __shfl_xor_sync(0xffffffffu, rs1, 2);
            l0 = l0 * sc0 + rs0;
            l1 = l1 * sc1 + rs1;

            // PV: P frags from sacc (register identity), V frags via ldmatrix
            #pragma unroll
            for (int j = 0; j < 4; j++) {
                uint32_t pah[4], pal[4];
                split2(sacc[2 * j][0],     sacc[2 * j][1],     pah[0], pal[0]);
                split2(sacc[2 * j][2],     sacc[2 * j][3],     pah[1], pal[1]);
                split2(sacc[2 * j + 1][0], sacc[2 * j + 1][1], pah[2], pal[2]);
                split2(sacc[2 * j + 1][2], sacc[2 * j + 1][3], pah[3], pal[3]);
                #pragma unroll
                for (int np = 0; np < 4; np++) {
                    uint32_t vh4[4], vl4[4];
                    uint32_t va = stg + 2 * AMAT + np * 2304 + boff + j * 32;
                    ldsm_x4(vh4, va);
                    ldsm_x4(vl4, va + AMAT);
                    uint32_t bh0[2] = {vh4[0], vh4[2]}, bh1[2] = {vh4[1], vh4[3]};
                    uint32_t bl0[2] = {vl4[0], vl4[2]}, bl1[2] = {vl4[1], vl4[3]};
                    mma_bf16(oacc[2 * np], pah, bh0);
                    mma_bf16(oacc[2 * np], pal, bh0);
                    mma_bf16(oacc[2 * np], pah, bl0);
                    mma_bf16(oacc[2 * np + 1], pah, bh1);
                    mma_bf16(oacc[2 * np + 1], pal, bh1);
                    mma_bf16(oacc[2 * np + 1], pah, bl1);
                }
            }
        }
        __syncthreads();
    }

    // epilogue: O = oacc / l, write bf16 hi/lo directly (feeds O-projection)
    float il0 = (l0 > 0.f) ? 1.f / l0 : 0.f;
    float il1 = (l1 > 0.f) ? 1.f / l1 : 0.f;
    size_t row0 = (size_t)b * SEQ + qb * 128 + w * 16 + (lane >> 2);
    size_t row1 = row0 + 8;
    #pragma unroll
    for (int nt = 0; nt < 8; nt++) {
        int colg = h * HD + nt * 8 + (lane & 3) * 2;
        uint32_t hi, lo;
        split2(oacc[nt][0] * il0, oacc[nt][1] * il0, hi, lo);
        *(uint32_t*)(Oh + row0 * HIDDEN + colg) = hi;
        *(uint32_t*)(Ol + row0 * HIDDEN + colg) = lo;
        split2(oacc[nt][2] * il1, oacc[nt][3] * il1, hi, lo);
        *(uint32_t*)(Oh + row1 * HIDDEN + colg) = hi;
        *(uint32_t*)(Ol + row1 * HIDDEN + colg) = lo;
    }
}

// ---------------- launcher ----------------
extern "C" void kernel_launch(void* const* d_in, const int* in_sizes, int n_in,
                              void* d_out, int out_size)
{
    const float* X  = (const float*)d_in[0];
    const int*   mk = (const int*)  d_in[1];
    const float* Wq = (const float*)d_in[2];
    const float* bq = (const float*)d_in[3];
    const float* Wk = (const float*)d_in[4];
    const float* bk = (const float*)d_in[5];
    const float* Wv = (const float*)d_in[6];
    const float* bv = (const float*)d_in[7];
    const float* Wo = (const float*)d_in[8];
    const float* bo = (const float*)d_in[9];
    float* out = (float*)d_out;

    float *qp, *kp, *vp;
    cudaGetSymbolAddress((void**)&qp, g_Q);
    cudaGetSymbolAddress((void**)&kp, g_K);
    cudaGetSymbolAddress((void**)&vp, g_V);

    __nv_bfloat16 *x0, *x1, *wq0, *wq1, *wk0, *wk1, *wv0, *wv1, *wo0, *wo1;
    __nv_bfloat16 *qh, *ql, *kh, *kl, *vth, *vtl;
    cudaGetSymbolAddress((void**)&x0, g_X0);
    cudaGetSymbolAddress((void**)&x1, g_X1);
    cudaGetSymbolAddress((void**)&wq0, g_Wq0);
    cudaGetSymbolAddress((void**)&wq1, g_Wq1);
    cudaGetSymbolAddress((void**)&wk0, g_Wk0);
    cudaGetSymbolAddress((void**)&wk1, g_Wk1);
    cudaGetSymbolAddress((void**)&wv0, g_Wv0);
    cudaGetSymbolAddress((void**)&wv1, g_Wv1);
    cudaGetSymbolAddress((void**)&wo0, g_Wo0);
    cudaGetSymbolAddress((void**)&wo1, g_Wo1);
    cudaGetSymbolAddress((void**)&qh, g_Qh);
    cudaGetSymbolAddress((void**)&ql, g_Ql);
    cudaGetSymbolAddress((void**)&kh, g_Kh);
    cudaGetSymbolAddress((void**)&kl, g_Kl);
    cudaGetSymbolAddress((void**)&vth, g_Vth);
    cudaGetSymbolAddress((void**)&vtl, g_Vtl);

    cudaFuncSetAttribute(gemm_mma, cudaFuncAttributeMaxDynamicSharedMemorySize, GEMM_SMEM);
    cudaFuncSetAttribute(attn_mma, cudaFuncAttributeMaxDynamicSharedMemorySize, ATTN_SMEM);

    // weight transposes + splits
    wtrans_kernel<<<dim3(HIDDEN/32, HIDDEN/32), dim3(32,8)>>>(Wq, wq0, wq1, HIDDEN, HIDDEN);
    wtrans_kernel<<<dim3(KVW/32,    HIDDEN/32), dim3(32,8)>>>(Wk, wk0, wk1, HIDDEN, KVW);
    wtrans_kernel<<<dim3(KVW/32,    HIDDEN/32), dim3(32,8)>>>(Wv, wv0, wv1, HIDDEN, KVW);
    wtrans_kernel<<<dim3(HIDDEN/32, HIDDEN/32), dim3(32,8)>>>(Wo, wo0, wo1, HIDDEN, HIDDEN);

    // split input activations
    {
        int n4 = MROWS * HIDDEN / 4;
        split_kernel<<<(n4 + 255) / 256, 256>>>(X, x0, x1, n4);
    }

    // projections (HMMA bf16x3)
    gemm_mma<<<dim3(HIDDEN/GBN, MROWS/GBM), 256, GEMM_SMEM>>>(x0, x1, wq0, wq1, bq, qp, HIDDEN, HIDDEN);
    gemm_mma<<<dim3(KVW/GBN,    MROWS/GBM), 256, GEMM_SMEM>>>(x0, x1, wk0, wk1, bk, kp, KVW, HIDDEN);
    gemm_mma<<<dim3(KVW/GBN,    MROWS/GBM), 256, GEMM_SMEM>>>(x0, x1, wv0, wv1, bv, vp, KVW, HIDDEN);

    // RoPE table + fused rope/split for Q,K; split+transpose for V
    rope_table<<<(SEQ * HD + 255) / 256, 256>>>();
    rope_split<<<((size_t)MROWS * NHEADS * 32 + 255) / 256, 256>>>(qp, qh, ql, NHEADS);
    rope_split<<<((size_t)MROWS * NKV    * 32 + 255) / 256, 256>>>(kp, kh, kl, NKV);
    vsplit_t<<<dim3(SEQ/32, HD/32, BATCH*NKV), dim3(32,8)>>>(vp, vth, vtl);

    // HMMA flash attention — writes bf16 hi/lo straight into O-proj A buffers
    attn_mma<<<dim3(SEQ/128, NHEADS, BATCH), 256, ATTN_SMEM>>>(qh, ql, kh, kl, vth, vtl,
                                                               mk, x0, x1);

    // output projection
    gemm_mma<<<dim3(HIDDEN/GBN, MROWS/GBM), 256, GEMM_SMEM>>>(x0, x1, wo0, wo1, bo, out, HIDDEN, HIDDEN);
}

// round 5
// speedup vs baseline: 2.7175x; 1.0612x over previous
#include <cuda_runtime.h>
#include <cuda_bf16.h>
#include <math.h>
#include <stdint.h>

#define HIDDEN 1024
#define NHEADS 16
#define NKV 4
#define HD 64
#define BATCH 2
#define SEQ 2048
#define MROWS (BATCH*SEQ)     // 4096
#define KVW (NKV*HD)          // 256
#define NQKV 1536             // 1024 + 256 + 256

// ---------------- scratch (no allocations allowed) ----------------
__device__ float g_Q[(size_t)MROWS*HIDDEN];
__device__ float g_K[(size_t)MROWS*KVW];
__device__ float g_V[(size_t)MROWS*KVW];
__device__ float g_cos[SEQ*HD];
__device__ float g_sin[SEQ*HD];

// bf16 hi/lo split buffers
__device__ __align__(16) __nv_bfloat16 g_X0[(size_t)MROWS*HIDDEN];
__device__ __align__(16) __nv_bfloat16 g_X1[(size_t)MROWS*HIDDEN];
__device__ __align__(16) __nv_bfloat16 g_WT0[(size_t)NQKV*HIDDEN];  // [Wq;Wk;Wv]^T
__device__ __align__(16) __nv_bfloat16 g_WT1[(size_t)NQKV*HIDDEN];
__device__ __align__(16) __nv_bfloat16 g_Wo0[(size_t)HIDDEN*HIDDEN];
__device__ __align__(16) __nv_bfloat16 g_Wo1[(size_t)HIDDEN*HIDDEN];
// attention operand buffers (bf16 hi/lo)
__device__ __align__(16) __nv_bfloat16 g_Qh[(size_t)MROWS*HIDDEN];
__device__ __align__(16) __nv_bfloat16 g_Ql[(size_t)MROWS*HIDDEN];
__device__ __align__(16) __nv_bfloat16 g_Kh[(size_t)MROWS*KVW];
__device__ __align__(16) __nv_bfloat16 g_Kl[(size_t)MROWS*KVW];
__device__ __align__(16) __nv_bfloat16 g_Vth[(size_t)MROWS*KVW];  // [b][kv][hd][seq]
__device__ __align__(16) __nv_bfloat16 g_Vtl[(size_t)MROWS*KVW];

// ================= small PTX helpers =================
__device__ __forceinline__ void cp_async16(uint32_t saddr, const void* gaddr) {
    asm volatile("cp.async.ca.shared.global [%0], [%1], 16;"
                 :: "r"(saddr), "l"(gaddr));
}
__device__ __forceinline__ void cp_commit() {
    asm volatile("cp.async.commit_group;");
}
__device__ __forceinline__ void cp_wait0() {
    asm volatile("cp.async.wait_group 0;");
}
__device__ __forceinline__ void cp_wait1() {
    asm volatile("cp.async.wait_group 1;");
}
__device__ __forceinline__ void ldsm_x4(uint32_t* r, uint32_t addr) {
    asm volatile("ldmatrix.sync.aligned.m8n8.x4.shared.b16 {%0,%1,%2,%3}, [%4];"
                 : "=r"(r[0]), "=r"(r[1]), "=r"(r[2]), "=r"(r[3]) : "r"(addr));
}
__device__ __forceinline__ void mma_bf16(float* c, const uint32_t* a, const uint32_t* b) {
    asm volatile("mma.sync.aligned.m16n8k16.row.col.f32.bf16.bf16.f32 "
                 "{%0,%1,%2,%3}, {%4,%5,%6,%7}, {%8,%9}, {%0,%1,%2,%3};"
                 : "+f"(c[0]), "+f"(c[1]), "+f"(c[2]), "+f"(c[3])
                 : "r"(a[0]), "r"(a[1]), "r"(a[2]), "r"(a[3]),
                   "r"(b[0]), "r"(b[1]));
}
__device__ __forceinline__ void split2(float x, float y, uint32_t& hi, uint32_t& lo) {
    __nv_bfloat162 h = __floats2bfloat162_rn(x, y);
    float rx = x - __bfloat162float(h.x);
    float ry = y - __bfloat162float(h.y);
    __nv_bfloat162 l = __floats2bfloat162_rn(rx, ry);
    hi = *reinterpret_cast<uint32_t*>(&h);
    lo = *reinterpret_cast<uint32_t*>(&l);
}

// ================= prep kernels =================

__global__ void split_kernel(const float* __restrict__ X, __nv_bfloat16* __restrict__ H,
                             __nv_bfloat16* __restrict__ L, int n4)
{
    int i = blockIdx.x * blockDim.x + threadIdx.x;
    if (i >= n4) return;
    float4 v = ((const float4*)X)[i];
    float f[4] = {v.x, v.y, v.z, v.w};
    __nv_bfloat16 h[4], l[4];
    #pragma unroll
    for (int j = 0; j < 4; j++) {
        h[j] = __float2bfloat16(f[j]);
        l[j] = __float2bfloat16(f[j] - __bfloat162float(h[j]));
    }
    __nv_bfloat162* H2 = (__nv_bfloat162*)H;
    __nv_bfloat162* L2 = (__nv_bfloat162*)L;
    H2[2*i+0] = __nv_bfloat162{h[0], h[1]};
    H2[2*i+1] = __nv_bfloat162{h[2], h[3]};
    L2[2*i+0] = __nv_bfloat162{l[0], l[1]};
    L2[2*i+1] = __nv_bfloat162{l[2], l[3]};
}

// all 4 weights in one launch: z=0 Wq->WT[0:1024], z=1 Wk->WT[1024:1280],
// z=2 Wv->WT[1280:1536], z=3 Wo->WO[0:1024]. All K=1024.
__global__ void wtrans_all(const float* __restrict__ Wq, const float* __restrict__ Wk,
                           const float* __restrict__ Wv, const float* __restrict__ Wo,
                           __nv_bfloat16* __restrict__ WT0, __nv_bfloat16* __restrict__ WT1,
                           __nv_bfloat16* __restrict__ WO0, __nv_bfloat16* __restrict__ WO1)
{
    int z = blockIdx.z;
    const float* src;
    __nv_bfloat16 *H, *L;
    int Nsrc, rofs;
    if (z == 0)      { src = Wq; Nsrc = 1024; rofs = 0;    H = WT0; L = WT1; }
    else if (z == 1) { src = Wk; Nsrc = 256;  rofs = 1024; H = WT0; L = WT1; }
    else if (z == 2) { src = Wv; Nsrc = 256;  rofs = 1280; H = WT0; L = WT1; }
    else             { src = Wo; Nsrc = 1024; rofs = 0;    H = WO0; L = WO1; }

    int nb = blockIdx.x * 32, kb = blockIdx.y * 32;
    if (nb >= Nsrc) return;
    __shared__ float t[32][33];
    int tx = threadIdx.x, ty = threadIdx.y;   // 32 x 8
    #pragma unroll
    for (int r = 0; r < 32; r += 8)
        t[ty + r][tx] = src[(size_t)(kb + ty + r) * Nsrc + nb + tx];
    __syncthreads();
    #pragma unroll
    for (int r = 0; r < 32; r += 8) {
        float v = t[tx][ty + r];
        __nv_bfloat16 h = __float2bfloat16(v);
        size_t o = (size_t)(rofs + nb + ty + r) * HIDDEN + kb + tx;
        H[o] = h;
        L[o] = __float2bfloat16(v - __bfloat162float(h));
    }
}

// ================= HMMA bf16x3 GEMM, tile 128x256x32 =================
// K fixed = 1024. Epilogue routes columns: [0,1024)->Cq(w=1024,bq),
// [1024,1280)->Ck(w=256,bk), [1280,1536)->Cv(w=256,bv).
#define GBM 128
#define GBN 256
#define GBK 32
#define GP 80                      // row pitch bytes (40 bf16)
#define A_BYTES (128*GP)           // 10240
#define B_BYTES (256*GP)           // 20480
#define STG_BYTES (2*A_BYTES + 2*B_BYTES)   // 61440
#define GEMM_SMEM (2*STG_BYTES)             // 122880

__device__ __forceinline__ void gemm_stage_issue(
    uint32_t sb, const __nv_bfloat16* A0, const __nv_bfloat16* A1,
    const __nv_bfloat16* B0, const __nv_bfloat16* B1,
    int m0, int n0, int k0, int tid)
{
    #pragma unroll
    for (int i = 0; i < 12; i++) {
        int idx = tid + i * 256;          // 0..3071
        if (idx < 1024) {
            int m = idx >> 9;             // 0:A0 1:A1
            int r = (idx >> 2) & 127, c = idx & 3;
            const __nv_bfloat16* src = (m ? A1 : A0) + (size_t)(m0 + r) * HIDDEN + k0 + c * 8;
            cp_async16(sb + m * A_BYTES + r * GP + c * 16, src);
        } else {
            int j = idx - 1024;
            int m = j >> 10;              // 0:B0 1:B1
            int r = (j >> 2) & 255, c = j & 3;
            const __nv_bfloat16* src = (m ? B1 : B0) + (size_t)(n0 + r) * HIDDEN + k0 + c * 8;
            cp_async16(sb + 2 * A_BYTES + m * B_BYTES + r * GP + c * 16, src);
        }
    }
    cp_commit();
}

__global__ __launch_bounds__(256, 1)
void gemm_big(const __nv_bfloat16* __restrict__ A0, const __nv_bfloat16* __restrict__ A1,
              const __nv_bfloat16* __restrict__ B0, const __nv_bfloat16* __restrict__ B1,
              const float* __restrict__ bq, const float* __restrict__ bk,
              const float* __restrict__ bv,
              float* __restrict__ Cq, float* __restrict__ Ck, float* __restrict__ Cv)
{
    extern __shared__ char dsm[];
    uint32_t sbu = (uint32_t)__cvta_generic_to_shared(dsm);

    int tid = threadIdx.x;
    int wid = tid >> 5, lane = tid & 31;
    int wm = wid >> 2;            // 0..1 -> 64 rows
    int wn = wid & 3;             // 0..3 -> 64 cols
    int m0 = blockIdx.y * GBM, n0 = blockIdx.x * GBN;

    float acc[4][8][4];
    #pragma unroll
    for (int i = 0; i < 4; i++)
        #pragma unroll
        for (int j = 0; j < 8; j++)
            #pragma unroll
            for (int k = 0; k < 4; k++) acc[i][j][k] = 0.f;

    const int NIT = HIDDEN / GBK;   // 32

    gemm_stage_issue(sbu, A0, A1, B0, B1, m0, n0, 0, tid);
    cp_wait0();
    __syncthreads();

    uint32_t aRow = (uint32_t)(wm * 64 + (lane & 15));
    uint32_t aColB = (uint32_t)((lane >> 4) * 16);
    uint32_t bRow = (uint32_t)(wn * 64 + ((lane >> 4) * 8) + (lane & 7));
    uint32_t bColB = (uint32_t)(((lane >> 3) & 1) * 16);

    int s = 0;
    for (int it = 0; it < NIT; it++) {
        if (it + 1 < NIT)
            gemm_stage_issue(sbu + (s ^ 1) * STG_BYTES, A0, A1, B0, B1,
                             m0, n0, (it + 1) * GBK, tid);

        uint32_t base = sbu + s * STG_BYTES;
        #pragma unroll
        for (int kk = 0; kk < 2; kk++) {
            uint32_t kOffB = (uint32_t)(kk * 32);
            uint32_t a0f[4][4], a1f[4][4];
            #pragma unroll
            for (int mt = 0; mt < 4; mt++) {
                uint32_t ad = base + (aRow + mt * 16) * GP + kOffB + aColB;
                ldsm_x4(a0f[mt], ad);
                ldsm_x4(a1f[mt], ad + A_BYTES);
            }
            #pragma unroll
            for (int nt2 = 0; nt2 < 4; nt2++) {
                uint32_t bd = base + 2 * A_BYTES + (bRow + nt2 * 16) * GP + kOffB + bColB;
                uint32_t t0[4], t1[4];
                ldsm_x4(t0, bd);
                ldsm_x4(t1, bd + B_BYTES);
                uint32_t bh0[2] = {t0[0], t0[1]}, bh1[2] = {t0[2], t0[3]};
                uint32_t bl0[2] = {t1[0], t1[1]}, bl1[2] = {t1[2], t1[3]};
                #pragma unroll
                for (int mt = 0; mt < 4; mt++) {
                    mma_bf16(acc[mt][2 * nt2],     a0f[mt], bh0);
                    mma_bf16(acc[mt][2 * nt2],     a1f[mt], bh0);
                    mma_bf16(acc[mt][2 * nt2],     a0f[mt], bl0);
                    mma_bf16(acc[mt][2 * nt2 + 1], a0f[mt], bh1);
                    mma_bf16(acc[mt][2 * nt2 + 1], a1f[mt], bh1);
                    mma_bf16(acc[mt][2 * nt2 + 1], a0f[mt], bl1);
                }
            }
        }
        if (it + 1 < NIT) cp_wait0();
        __syncthreads();
        s ^= 1;
    }

    // epilogue with column routing
    #pragma unroll
    for (int mt = 0; mt < 4; mt++) {
        int row0 = m0 + wm * 64 + mt * 16 + (lane >> 2);
        #pragma unroll
        for (int nt = 0; nt < 8; nt++) {
            int gcol = n0 + wn * 64 + nt * 8 + (lane & 3) * 2;
            float* dst; const float* bp; int W, lcol;
            if (gcol < 1024)      { dst = Cq; bp = bq; W = 1024; lcol = gcol; }
            else if (gcol < 1280) { dst = Ck; bp = bk; W = 256;  lcol = gcol - 1024; }
            else                  { dst = Cv; bp = bv; W = 256;  lcol = gcol - 1280; }
            float2 bb = *(const float2*)(bp + lcol);
            float2 o0 = {acc[mt][nt][0] + bb.x, acc[mt][nt][1] + bb.y};
            float2 o1 = {acc[mt][nt][2] + bb.x, acc[mt][nt][3] + bb.y};
            *(float2*)(dst + (size_t)row0 * W + lcol) = o0;
            *(float2*)(dst + (size_t)(row0 + 8) * W + lcol) = o1;
        }
    }
}

// ---------------- RoPE table ----------------
__global__ void rope_table()
{
    __shared__ double dinv[32];
    int tid = threadIdx.x;
    if (tid < 32) dinv[tid] = exp(-((double)tid / 32.0) * log(100000.0));
    __syncthreads();
    int idx = blockIdx.x * blockDim.x + tid;
    if (idx >= SEQ * HD) return;
    int t = idx >> 6;
    int j = idx & 63;
    int m = j & 31;
    float af = (float)((double)t * dinv[m]);
    float s, c;
    sincosf(af, &s, &c);
    g_cos[idx] = c;
    g_sin[idx] = s;
}

// ---------------- RoPE apply + split to bf16 hi/lo ----------------
__global__ void rope_split(const float* __restrict__ X, __nv_bfloat16* __restrict__ H,
                           __nv_bfloat16* __restrict__ L, int nheads)
{
    int idx = blockIdx.x * blockDim.x + threadIdx.x;
    int total = MROWS * nheads * 32;
    if (idx >= total) return;
    int pair = idx & 31;
    int tmp  = idx >> 5;
    int head = tmp % nheads;
    int row  = tmp / nheads;
    int t = row & (SEQ - 1);
    size_t off = (size_t)row * nheads * HD + head * HD + pair * 2;
    const float* p = X + off;
    float x0 = p[0], x1 = p[1];
    int j0 = pair * 2, j1 = pair * 2 + 1;
    float c0 = g_cos[t * HD + j0], s0 = g_sin[t * HD + j0];
    float c1 = g_cos[t * HD + j1], s1 = g_sin[t * HD + j1];
    float r0 = x0 * c0 - x1 * s0;
    float r1 = x1 * c1 + x0 * s1;
    uint32_t hi, lo;
    split2(r0, r1, hi, lo);
    *(uint32_t*)(H + off) = hi;
    *(uint32_t*)(L + off) = lo;
}

// ---------------- V: split + transpose to [b][kv][hd][seq] ----------------
__global__ void vsplit_t(const float* __restrict__ V, __nv_bfloat16* __restrict__ H,
                         __nv_bfloat16* __restrict__ L)
{
    __shared__ float t[32][33];
    int s0 = blockIdx.x * 32;
    int c0 = blockIdx.y * 32;
    int bkv = blockIdx.z;
    int b = bkv >> 2, kv = bkv & 3;
    int tx = threadIdx.x, ty = threadIdx.y;
    #pragma unroll
    for (int r = 0; r < 32; r += 8)
        t[ty + r][tx] = V[((size_t)(b * SEQ + s0 + ty + r) * NKV + kv) * HD + c0 + tx];
    __syncthreads();
    #pragma unroll
    for (int r = 0; r < 32; r += 8) {
        float v = t[tx][ty + r];
        __nv_bfloat16 h = __float2bfloat16(v);
        size_t o = ((size_t)(b * NKV + kv) * HD + c0 + ty + r) * SEQ + s0 + tx;
        H[o] = h;
        L[o] = __float2bfloat16(v - __bfloat162float(h));
    }
}

// ================= HMMA flash attention (bf16x3, causal, GQA) =================
#define AMAT 9216
#define ASTG (4*AMAT)
#define AQ_BYTES 36864
#define AMASK_OFF (AQ_BYTES + 2*ASTG)
#define ATTN_SMEM (AMASK_OFF + 512)

__device__ __forceinline__ void attn_issue_kv(
    uint32_t sbuf, const __nv_bfloat16* Kh, const __nv_bfloat16* Kl,
    const __nv_bfloat16* Vh, const __nv_bfloat16* Vl,
    int b, int kv, int it, int tid)
{
    #pragma unroll
    for (int i = 0; i < 8; i++) {
        int c = tid + i * 256;
        int m = c >> 9;
        int r = (c >> 3) & 63;
        int col = c & 7;
        const __nv_bfloat16* src;
        if (m == 0)      src = Kh + ((size_t)(b * SEQ + it * 64 + r) * NKV + kv) * HD + col * 8;
        else if (m == 1) src = Kl + ((size_t)(b * SEQ + it * 64 + r) * NKV + kv) * HD + col * 8;
        else if (m == 2) src = Vh + ((size_t)(b * NKV + kv) * HD + r) * SEQ + it * 64 + col * 8;
        else             src = Vl + ((size_t)(b * NKV + kv) * HD + r) * SEQ + it * 64 + col * 8;
        cp_async16(sbuf + m * AMAT + r * 144 + col * 16, src);
    }
}

__global__ __launch_bounds__(256)
void attn_mma(const __nv_bfloat16* __restrict__ Qh, const __nv_bfloat16* __restrict__ Ql,
              const __nv_bfloat16* __restrict__ Kh, const __nv_bfloat16* __restrict__ Kl,
              const __nv_bfloat16* __restrict__ Vh, const __nv_bfloat16* __restrict__ Vl,
              const int* __restrict__ mask,
              __nv_bfloat16* __restrict__ Oh, __nv_bfloat16* __restrict__ Ol)
{
    extern __shared__ char smc[];
    uint32_t sb = (uint32_t)__cvta_generic_to_shared(smc);
    float* maskf = (float*)(smc + AMASK_OFF);

    int tid = threadIdx.x, w = tid >> 5, lane = tid & 31;
    int qb = blockIdx.x, h = blockIdx.y, b = blockIdx.z, kv = h >> 2;
    int niter = 2 * qb + 2;

    #pragma unroll
    for (int i = 0; i < 8; i++) {
        int c = tid + i * 256;
        int m = c >> 10;
        int r = (c >> 3) & 127;
        int col = c & 7;
        const __nv_bfloat16* src = (m ? Ql : Qh)
            + ((size_t)(b * SEQ + qb * 128 + r) * NHEADS + h) * HD + col * 8;
        cp_async16(sb + m * 18432 + r * 144 + col * 16, src);
    }
    attn_issue_kv(sb + AQ_BYTES, Kh, Kl, Vh, Vl, b, kv, 0, tid);
    if (tid < 64) maskf[tid] = (float)mask[b * SEQ + tid];
    cp_commit();

    uint32_t aoff = (uint32_t)((w * 16 + (lane & 15)) * 144 + (lane >> 4) * 16);
    uint32_t boff = (uint32_t)((lane & 15) * 144 + (lane >> 4) * 16);
    int rg0 = qb * 128 + w * 16 + (lane >> 2);
    int rg1 = rg0 + 8;

    float oacc[8][4];
    #pragma unroll
    for (int i = 0; i < 8; i++)
        #pragma unroll
        for (int j = 0; j < 4; j++) oacc[i][j] = 0.f;
    float m0 = -1e30f, m1 = -1e30f, l0 = 0.f, l1 = 0.f;

    for (int it = 0; it < niter; it++) {
        int s = it & 1;
        if (it + 1 < niter) {
            attn_issue_kv(sb + AQ_BYTES + (s ^ 1) * ASTG, Kh, Kl, Vh, Vl, b, kv, it + 1, tid);
            if (tid < 64) maskf[(s ^ 1) * 64 + tid] = (float)mask[b * SEQ + (it + 1) * 64 + tid];
            cp_commit();
            cp_wait1();
        } else {
            cp_wait0();
        }
        __syncthreads();

        if (it * 64 <= qb * 128 + w * 16 + 15) {
            uint32_t stg = sb + AQ_BYTES + s * ASTG;
            float sacc[8][4];
            #pragma unroll
            for (int i = 0; i < 8; i++)
                #pragma unroll
                for (int j = 0; j < 4; j++) sacc[i][j] = 0.f;

            uint32_t qhB = sb + aoff, qlB = sb + 18432 + aoff;
            #pragma unroll
            for (int ks = 0; ks < 4; ks++) {
                uint32_t ah[4], al4[4];
                ldsm_x4(ah, qhB + ks * 32);
                ldsm_x4(al4, qlB + ks * 32);
                #pragma unroll
                for (int np = 0; np < 4; np++) {
                    uint32_t kh4[4], kl4[4];
                    uint32_t ka = stg + np * 2304 + boff + ks * 32;
                    ldsm_x4(kh4, ka);
                    ldsm_x4(kl4, ka + AMAT);
                    uint32_t bh0[2] = {kh4[0], kh4[2]}, bh1[2] = {kh4[1], kh4[3]};
                    uint32_t bl0[2] = {kl4[0], kl4[2]}, bl1[2] = {kl4[1], kl4[3]};
                    mma_bf16(sacc[2 * np], ah, bh0);
                    mma_bf16(sacc[2 * np], al4, bh0);
                    mma_bf16(sacc[2 * np], ah, bl0);
                    mma_bf16(sacc[2 * np + 1], ah, bh1);
                    mma_bf16(sacc[2 * np + 1], al4, bh1);
                    mma_bf16(sacc[2 * np + 1], ah, bl1);
                }
            }

            const float* mk = maskf + s * 64;
            float mr0 = -1e30f, mr1 = -1e30f;
            #pragma unroll
            for (int nt = 0; nt < 8; nt++) {
                int cg = it * 64 + nt * 8 + (lane & 3) * 2;
                float km0 = mk[nt * 8 + (lane & 3) * 2];
                float km1 = mk[nt * 8 + (lane & 3) * 2 + 1];
                float v0 = sacc[nt][0] * 0.125f, v1 = sacc[nt][1] * 0.125f;
                float v2 = sacc[nt][2] * 0.125f, v3 = sacc[nt][3] * 0.125f;
                if (cg     > rg0 || km0 == 0.f) v0 = -1e30f;
                if (cg + 1 > rg0 || km1 == 0.f) v1 = -1e30f;
                if (cg     > rg1 || km0 == 0.f) v2 = -1e30f;
                if (cg + 1 > rg1 || km1 == 0.f) v3 = -1e30f;
                sacc[nt][0] = v0; sacc[nt][1] = v1; sacc[nt][2] = v2; sacc[nt][3] = v3;
                mr0 = fmaxf(mr0, fmaxf(v0, v1));
                mr1 = fmaxf(mr1, fmaxf(v2, v3));
            }
            mr0 = fmaxf(mr0, __shfl_xor_sync(0xffffffffu, mr0, 1));
            mr0 = fmaxf(mr0, __shfl_xor_sync(0xffffffffu, mr0, 2));
            mr1 = fmaxf(mr1, __shfl_xor_sync(0xffffffffu, mr1, 1));
            mr1 = fmaxf(mr1, __shfl_xor_sync(0xffffffffu, mr1, 2));

            float mn0 = fmaxf(m0, mr0), mn1 = fmaxf(m1, mr1);
            float sc0 = __expf(m0 - mn0), sc1 = __expf(m1 - mn1);
            float base0 = (mn0 < -5e29f) ? 0.f : mn0;
            float base1 = (mn1 < -5e29f) ? 0.f : mn1;
            m0 = mn0; m1 = mn1;

            float rs0 = 0.f, rs1 = 0.f;
            #pragma unroll
            for (int nt = 0; nt < 8; nt++) {
                float p0 = __expf(sacc[nt][0] - base0);
                float p1 = __expf(sacc[nt][1] - base0);
                float p2 = __expf(sacc[nt][2] - base1);
                float p3 = __expf(sacc[nt][3] - base1);
                sacc[nt][0] = p0; sacc[nt][1] = p1; sacc[nt][2] = p2; sacc[nt][3] = p3;
                rs0 += p0 + p1; rs1 += p2 + p3;
                oacc[nt][0] *= sc0; oacc[nt][1] *= sc0;
                oacc[nt][2] *= sc1; oacc[nt][3] *= sc1;
            }
            rs0 += __shfl_xor_sync(0xffffffffu, rs0, 1);
            rs0 += __shfl_xor_sync(0xffffffffu, rs0, 2);
            rs1 += __shfl_xor_sync(0xffffffffu, rs1, 1);
            rs1 += __shfl_xor_sync(0xffffffffu, rs1, 2);
            l0 = l0 * sc0 + rs0;
            l1 = l1 * sc1 + rs1;

            #pragma unroll
            for (int j = 0; j < 4; j++) {
                uint32_t pah[4], pal[4];
                split2(sacc[2 * j][0],     sacc[2 * j][1],     pah[0], pal[0]);
                split2(sacc[2 * j][2],     sacc[2 * j][3],     pah[1], pal[1]);
                split2(sacc[2 * j + 1][0], sacc[2 * j + 1][1], pah[2], pal[2]);
                split2(sacc[2 * j + 1][2], sacc[2 * j + 1][3], pah[3], pal[3]);
                #pragma unroll
                for (int np = 0; np < 4; np++) {
                    uint32_t vh4[4], vl4[4];
                    uint32_t va = stg + 2 * AMAT + np * 2304 + boff + j * 32;
                    ldsm_x4(vh4, va);
                    ldsm_x4(vl4, va + AMAT);
                    uint32_t bh0[2] = {vh4[0], vh4[2]}, bh1[2] = {vh4[1], vh4[3]};
                    uint32_t bl0[2] = {vl4[0], vl4[2]}, bl1[2] = {vl4[1], vl4[3]};
                    mma_bf16(oacc[2 * np], pah, bh0);
                    mma_bf16(oacc[2 * np], pal, bh0);
                    mma_bf16(oacc[2 * np], pah, bl0);
                    mma_bf16(oacc[2 * np + 1], pah, bh1);
                    mma_bf16(oacc[2 * np + 1], pal, bh1);
                    mma_bf16(oacc[2 * np + 1], pah, bl1);
                }
            }
        }
        __syncthreads();
    }

    float il0 = (l0 > 0.f) ? 1.f / l0 : 0.f;
    float il1 = (l1 > 0.f) ? 1.f / l1 : 0.f;
    size_t row0 = (size_t)b * SEQ + qb * 128 + w * 16 + (lane >> 2);
    size_t row1 = row0 + 8;
    #pragma unroll
    for (int nt = 0; nt < 8; nt++) {
        int colg = h * HD + nt * 8 + (lane & 3) * 2;
        uint32_t hi, lo;
        split2(oacc[nt][0] * il0, oacc[nt][1] * il0, hi, lo);
        *(uint32_t*)(Oh + row0 * HIDDEN + colg) = hi;
        *(uint32_t*)(Ol + row0 * HIDDEN + colg) = lo;
        split2(oacc[nt][2] * il1, oacc[nt][3] * il1, hi, lo);
        *(uint32_t*)(Oh + row1 * HIDDEN + colg) = hi;
        *(uint32_t*)(Ol + row1 * HIDDEN + colg) = lo;
    }
}

// ---------------- launcher ----------------
extern "C" void kernel_launch(void* const* d_in, const int* in_sizes, int n_in,
                              void* d_out, int out_size)
{
    const float* X  = (const float*)d_in[0];
    const int*   mk = (const int*)  d_in[1];
    const float* Wq = (const float*)d_in[2];
    const float* bq = (const float*)d_in[3];
    const float* Wk = (const float*)d_in[4];
    const float* bk = (const float*)d_in[5];
    const float* Wv = (const float*)d_in[6];
    const float* bv = (const float*)d_in[7];
    const float* Wo = (const float*)d_in[8];
    const float* bo = (const float*)d_in[9];
    float* out = (float*)d_out;

    float *qp, *kp, *vp;
    cudaGetSymbolAddress((void**)&qp, g_Q);
    cudaGetSymbolAddress((void**)&kp, g_K);
    cudaGetSymbolAddress((void**)&vp, g_V);

    __nv_bfloat16 *x0, *x1, *wt0, *wt1, *wo0, *wo1;
    __nv_bfloat16 *qh, *ql, *kh, *kl, *vth, *vtl;
    cudaGetSymbolAddress((void**)&x0, g_X0);
    cudaGetSymbolAddress((void**)&x1, g_X1);
    cudaGetSymbolAddress((void**)&wt0, g_WT0);
    cudaGetSymbolAddress((void**)&wt1, g_WT1);
    cudaGetSymbolAddress((void**)&wo0, g_Wo0);
    cudaGetSymbolAddress((void**)&wo1, g_Wo1);
    cudaGetSymbolAddress((void**)&qh, g_Qh);
    cudaGetSymbolAddress((void**)&ql, g_Ql);
    cudaGetSymbolAddress((void**)&kh, g_Kh);
    cudaGetSymbolAddress((void**)&kl, g_Kl);
    cudaGetSymbolAddress((void**)&vth, g_Vth);
    cudaGetSymbolAddress((void**)&vtl, g_Vtl);

    cudaFuncSetAttribute(gemm_big, cudaFuncAttributeMaxDynamicSharedMemorySize, GEMM_SMEM);
    cudaFuncSetAttribute(attn_mma, cudaFuncAttributeMaxDynamicSharedMemorySize, ATTN_SMEM);

    // all weight transposes + splits in one launch
    wtrans_all<<<dim3(32, 32, 4), dim3(32, 8)>>>(Wq, Wk, Wv, Wo, wt0, wt1, wo0, wo1);

    // split input activations
    {
        int n4 = MROWS * HIDDEN / 4;
        split_kernel<<<(n4 + 255) / 256, 256>>>(X, x0, x1, n4);
    }

    // fused QKV projection (HMMA bf16x3, 128x256 tiles)
    gemm_big<<<dim3(NQKV / GBN, MROWS / GBM), 256, GEMM_SMEM>>>(
        x0, x1, wt0, wt1, bq, bk, bv, qp, kp, vp);

    // RoPE + splits
    rope_table<<<(SEQ * HD + 255) / 256, 256>>>();
    rope_split<<<((size_t)MROWS * NHEADS * 32 + 255) / 256, 256>>>(qp, qh, ql, NHEADS);
    rope_split<<<((size_t)MROWS * NKV    * 32 + 255) / 256, 256>>>(kp, kh, kl, NKV);
    vsplit_t<<<dim3(SEQ/32, HD/32, BATCH*NKV), dim3(32,8)>>>(vp, vth, vtl);

    // HMMA flash attention — writes bf16 hi/lo straight into O-proj A buffers
    attn_mma<<<dim3(SEQ/128, NHEADS, BATCH), 256, ATTN_SMEM>>>(qh, ql, kh, kl, vth, vtl,
                                                               mk, x0, x1);

    // output projection
    gemm_big<<<dim3(HIDDEN / GBN, MROWS / GBM), 256, GEMM_SMEM>>>(
        x0, x1, wo0, wo1, bo, bk, bv, out, kp, vp);
}